// round 3
// baseline (speedup 1.0000x reference)
#include <cuda_runtime.h>

#define BB 4
#define NN 2048
#define INF 256
#define HH 8
#define DD 32
#define ALPHA 0.2f
#define JT 64

// scratch (allocation-free rule: __device__ globals)
__device__ float g_Wh[BB*HH*NN*DD];   // [b][h][n][d]
__device__ float g_es[BB*HH*NN];      // e_i
__device__ float g_ed[BB*HH*NN];      // e_j

// ---------------------------------------------------------------------------
// Kernel 1: Wh = x @ W per head, plus e_src = Wh·a[:D], e_dst = Wh·a[D:]
// grid (B*N/64, H), 256 threads. smem: x tile 64x256 (64KB) + W 256x32 (32KB)
// ---------------------------------------------------------------------------
__global__ __launch_bounds__(256) void k1_proj(const float* __restrict__ x,
                                               const float* __restrict__ W,
                                               const float* __restrict__ a) {
    extern __shared__ float sm[];
    float* xs = sm;                // [64][256]
    float* Ws = sm + 64 * INF;     // [256][32]
    const int h  = blockIdx.y;
    const int b  = blockIdx.x >> 5;
    const int n0 = (blockIdx.x & 31) * 64;
    const int t  = threadIdx.x;

    const float4* xg = (const float4*)(x + ((size_t)b * NN + n0) * INF);
    float4* xs4 = (float4*)xs;
#pragma unroll
    for (int l = 0; l < 16; l++) xs4[t + l * 256] = xg[t + l * 256];
    const float4* wg = (const float4*)(W + (size_t)h * INF * DD);
    float4* ws4 = (float4*)Ws;
#pragma unroll
    for (int l = 0; l < 8; l++) ws4[t + l * 256] = wg[t + l * 256];
    __syncthreads();

    const int d = t & 31;
    const int g = t >> 5;          // warp id: rows g*8..g*8+7
    float acc[8];
#pragma unroll
    for (int r = 0; r < 8; r++) acc[r] = 0.f;

    for (int kq = 0; kq < INF / 4; kq++) {
        const float w0 = Ws[(kq * 4 + 0) * DD + d];
        const float w1 = Ws[(kq * 4 + 1) * DD + d];
        const float w2 = Ws[(kq * 4 + 2) * DD + d];
        const float w3 = Ws[(kq * 4 + 3) * DD + d];
#pragma unroll
        for (int r = 0; r < 8; r++) {
            const float4 xv = *(const float4*)&xs[(g * 8 + r) * INF + kq * 4];
            acc[r] = fmaf(xv.x, w0, fmaf(xv.y, w1, fmaf(xv.z, w2, fmaf(xv.w, w3, acc[r]))));
        }
    }

    const float asrc = a[h * 2 * DD + d];
    const float adst = a[h * 2 * DD + DD + d];
#pragma unroll
    for (int r = 0; r < 8; r++) {
        const int n = n0 + g * 8 + r;
        g_Wh[(((size_t)b * HH + h) * NN + n) * DD + d] = acc[r];
        float es = acc[r] * asrc;
        float ed = acc[r] * adst;
#pragma unroll
        for (int off = 16; off; off >>= 1) {
            es += __shfl_xor_sync(0xffffffffu, es, off);
            ed += __shfl_xor_sync(0xffffffffu, ed, off);
        }
        if (d == 0) {
            g_es[((size_t)b * HH + h) * NN + n] = es;
            g_ed[((size_t)b * HH + h) * NN + n] = ed;
        }
    }
}

// ---------------------------------------------------------------------------
// Kernel 2: flash-style masked softmax + PV; thread = (i-row, head) pair,
// p stays in a register (no p smem, no second barrier), acc[32] = full d row.
// grid = B * (N/16) = 512 blocks, 128 threads.
// smem: wh_s [64j][8h][32d] XOR-swizzled 64KB | adj [16][72] 4.5KB | ed [64][8] 2KB
// ---------------------------------------------------------------------------
__global__ __launch_bounds__(128) void k2_attn(const int* __restrict__ adj,
                                               float* __restrict__ out) {
    extern __shared__ float sm[];
    float* wh_s = sm;                         // 16384 floats (XOR-swizzled on d-group)
    int*   adjs = (int*)(sm + 16384);         // [16][72] padded rows
    float* ed_s = sm + 16384 + 16 * 72;       // [64j][8h]

    const int b  = blockIdx.x >> 7;
    const int i0 = (blockIdx.x & 127) * 16;
    const int t  = threadIdx.x;
    const int i  = t >> 3;                    // 0..15
    const int h  = t & 7;                     // 0..7

    const float ei = g_es[((size_t)b * HH + h) * NN + i0 + i];
    float denom = 0.f;
    float acc[DD];
#pragma unroll
    for (int d = 0; d < DD; d++) acc[d] = 0.f;

    for (int jt = 0; jt < NN / JT; jt++) {
        const int j0 = jt * JT;
        // --- adj tile: 256 int4, 2 per thread, padded row stride 72 ---
#pragma unroll
        for (int l = 0; l < 2; l++) {
            const int idx = t + l * 128;
            const int row = idx >> 4, c = idx & 15;
            const int4 v = *(const int4*)(adj + ((size_t)b * NN + i0 + row) * NN + j0 + c * 4);
            *(int4*)&adjs[row * 72 + c * 4] = v;
        }
        // --- wh tile [j][h][d], d-group XOR-swizzled by h: 4096 float4 ---
#pragma unroll
        for (int l = 0; l < 32; l++) {
            const int idx = t + l * 128;
            const int jj = idx >> 6;
            const int hh = (idx >> 3) & 7;
            const int d4 = idx & 7;
            const float4 v =
                ((const float4*)g_Wh)[(((size_t)b * HH + hh) * NN + j0 + jj) * 8 + d4];
            *(float4*)&wh_s[jj * 256 + hh * 32 + ((d4 ^ hh) & 7) * 4] = v;
        }
        // --- ed tile transposed [j][h]: 512 floats, coalesced read ---
#pragma unroll
        for (int l = 0; l < 4; l++) {
            const int idx = t + l * 128;
            const int hh = idx >> 6, jj = idx & 63;
            ed_s[jj * 8 + hh] = g_ed[((size_t)b * HH + hh) * NN + j0 + jj];
        }
        __syncthreads();

        const int* arow = adjs + i * 72;
#pragma unroll 4
        for (int j = 0; j < JT; j++) {
            float s = ei + ed_s[j * 8 + h];
            s = fmaxf(s, ALPHA * s);
            const float p = arow[j] ? __expf(s) : 0.f;   // no max pass: |s| <~ 12
            denom += p;
            const float* wbase = &wh_s[j * 256 + h * 32];
#pragma unroll
            for (int dg = 0; dg < 8; dg++) {
                const float4 wv = *(const float4*)&wbase[((dg ^ h) & 7) * 4];
                acc[dg * 4 + 0] = fmaf(p, wv.x, acc[dg * 4 + 0]);
                acc[dg * 4 + 1] = fmaf(p, wv.y, acc[dg * 4 + 1]);
                acc[dg * 4 + 2] = fmaf(p, wv.z, acc[dg * 4 + 2]);
                acc[dg * 4 + 3] = fmaf(p, wv.w, acc[dg * 4 + 3]);
            }
        }
        __syncthreads();
    }

    const float rd = 1.f / denom;
    float* op = out + ((size_t)b * NN + i0 + i) * (HH * DD) + h * DD;
#pragma unroll
    for (int dg = 0; dg < 8; dg++) {
        float4 v;
        v.x = acc[dg * 4 + 0] * rd;
        v.y = acc[dg * 4 + 1] * rd;
        v.z = acc[dg * 4 + 2] * rd;
        v.w = acc[dg * 4 + 3] * rd;
        ((float4*)op)[dg] = v;
    }
}

extern "C" void kernel_launch(void* const* d_in, const int* in_sizes, int n_in,
                              void* d_out, int out_size) {
    const float* x   = (const float*)d_in[0];
    const int*   adj = (const int*)d_in[1];
    const float* W   = (const float*)d_in[2];
    const float* a   = (const float*)d_in[3];
    float* out = (float*)d_out;

    cudaFuncSetAttribute(k1_proj, cudaFuncAttributeMaxDynamicSharedMemorySize, 98304);
    cudaFuncSetAttribute(k2_attn, cudaFuncAttributeMaxDynamicSharedMemorySize, 72192);

    k1_proj<<<dim3(128, 8), 256, 98304>>>(x, W, a);
    k2_attn<<<512, 128, 72192>>>(adj, out);
}

// round 4
// speedup vs baseline: 2.0414x; 2.0414x over previous
#include <cuda_runtime.h>

#define BB 4
#define NN 2048
#define INF 256
#define HH 8
#define DD 32
#define SPLITS 4
#define JSPAN (NN / SPLITS)      // 512 j per split
#define JT 32                    // j-tile
#define NTILES (JSPAN / JT)      // 16
#define LOG2E 1.44269504f

// scratch (allocation-free rule: __device__ globals)
__device__ float g_Wh[BB*HH*NN*DD];            // [b][h][n][d]
__device__ float g_es[BB*HH*NN];               // e_i * log2e
__device__ float g_ed[BB*HH*NN];               // e_j * log2e
__device__ unsigned int g_adjp[BB*NN*(NN/32)]; // packed adj bits [b][i][j/32]
__device__ float g_part[SPLITS*BB*NN*HH*DD];   // partial unnormalized out
__device__ float g_den[SPLITS*BB*NN*HH];       // partial denominators

__device__ __forceinline__ unsigned long long fma2(unsigned long long a,
                                                   unsigned long long b,
                                                   unsigned long long c) {
    unsigned long long d;
    asm("fma.rn.f32x2 %0, %1, %2, %3;" : "=l"(d) : "l"(a), "l"(b), "l"(c));
    return d;
}
__device__ __forceinline__ unsigned long long packf2(float x) {
    unsigned long long d;
    asm("mov.b64 %0, {%1, %1};" : "=l"(d) : "f"(x));
    return d;
}
__device__ __forceinline__ float ex2(float x) {
    float r;
    asm("ex2.approx.ftz.f32 %0, %1;" : "=f"(r) : "f"(x));
    return r;
}

// ---------------------------------------------------------------------------
// Kernel 0: pack adj int32 -> bitmask. Each warp ballots 32 words.
// grid 2048 x 256.
// ---------------------------------------------------------------------------
__global__ __launch_bounds__(256) void k0_pack(const int* __restrict__ adj) {
    const int lane = threadIdx.x & 31;
    const int gw   = blockIdx.x * 8 + (threadIdx.x >> 5);
#pragma unroll 4
    for (int r = 0; r < 32; r++) {
        const size_t u = (size_t)gw * 32 + r;
        const int v = adj[u * 32 + lane];
        const unsigned int bal = __ballot_sync(0xffffffffu, v != 0);
        if (lane == 0) g_adjp[u] = bal;
    }
}

// ---------------------------------------------------------------------------
// Kernel 1: Wh = x @ W per head, plus e = Wh·a (pre-scaled by log2e).
// grid (B*N/64, H), 256 threads. smem: x 64x256 (64KB) + W 256x32 (32KB)
// ---------------------------------------------------------------------------
__global__ __launch_bounds__(256) void k1_proj(const float* __restrict__ x,
                                               const float* __restrict__ W,
                                               const float* __restrict__ a) {
    extern __shared__ float sm[];
    float* xs = sm;                // [64][256]
    float* Ws = sm + 64 * INF;     // [256][32]
    const int h  = blockIdx.y;
    const int b  = blockIdx.x >> 5;
    const int n0 = (blockIdx.x & 31) * 64;
    const int t  = threadIdx.x;

    const float4* xg = (const float4*)(x + ((size_t)b * NN + n0) * INF);
    float4* xs4 = (float4*)xs;
#pragma unroll
    for (int l = 0; l < 16; l++) xs4[t + l * 256] = xg[t + l * 256];
    const float4* wg = (const float4*)(W + (size_t)h * INF * DD);
    float4* ws4 = (float4*)Ws;
#pragma unroll
    for (int l = 0; l < 8; l++) ws4[t + l * 256] = wg[t + l * 256];
    __syncthreads();

    const int d = t & 31;
    const int g = t >> 5;
    float acc[8];
#pragma unroll
    for (int r = 0; r < 8; r++) acc[r] = 0.f;

    for (int kq = 0; kq < INF / 4; kq++) {
        const float w0 = Ws[(kq * 4 + 0) * DD + d];
        const float w1 = Ws[(kq * 4 + 1) * DD + d];
        const float w2 = Ws[(kq * 4 + 2) * DD + d];
        const float w3 = Ws[(kq * 4 + 3) * DD + d];
#pragma unroll
        for (int r = 0; r < 8; r++) {
            const float4 xv = *(const float4*)&xs[(g * 8 + r) * INF + kq * 4];
            acc[r] = fmaf(xv.x, w0, fmaf(xv.y, w1, fmaf(xv.z, w2, fmaf(xv.w, w3, acc[r]))));
        }
    }

    const float asrc = a[h * 2 * DD + d];
    const float adst = a[h * 2 * DD + DD + d];
#pragma unroll
    for (int r = 0; r < 8; r++) {
        const int n = n0 + g * 8 + r;
        g_Wh[(((size_t)b * HH + h) * NN + n) * DD + d] = acc[r];
        float es = acc[r] * asrc;
        float ed = acc[r] * adst;
#pragma unroll
        for (int off = 16; off; off >>= 1) {
            es += __shfl_xor_sync(0xffffffffu, es, off);
            ed += __shfl_xor_sync(0xffffffffu, ed, off);
        }
        if (d == 0) {
            g_es[((size_t)b * HH + h) * NN + n] = es * LOG2E;
            g_ed[((size_t)b * HH + h) * NN + n] = ed * LOG2E;
        }
    }
}

// ---------------------------------------------------------------------------
// Kernel 2: masked softmax-numerator + PV partials with FFMA2.
// grid (32 i-tiles, B, SPLITS), 256 threads. Thread = (ip, h), 2 rows each.
// smem: wh_s [32j][8h][32d] XOR-swizzled 32KB | ed_s [32j][8h] 1KB
// ---------------------------------------------------------------------------
__global__ __launch_bounds__(256, 2) void k2_attn() {
    extern __shared__ float sm[];
    float* wh_s = sm;                    // 8192 floats
    float* ed_s = sm + JT * 256;         // [j][h]

    const int b  = blockIdx.y;
    const int s  = blockIdx.z;
    const int i0 = blockIdx.x * 64;
    const int t  = threadIdx.x;
    const int h  = t & 7;
    const int ip = t >> 3;               // 0..31
    const int row0 = i0 + ip * 2;

    const float ei0 = g_es[((size_t)b * HH + h) * NN + row0];
    const float ei1 = g_es[((size_t)b * HH + h) * NN + row0 + 1];
    const unsigned int* ap0 = g_adjp + ((size_t)b * NN + row0) * (NN / 32) + s * NTILES;
    const unsigned int* ap1 = ap0 + (NN / 32);

    float den0 = 0.f, den1 = 0.f;
    unsigned long long acc0[16], acc1[16];
#pragma unroll
    for (int k = 0; k < 16; k++) { acc0[k] = 0ull; acc1[k] = 0ull; }

    for (int jt = 0; jt < NTILES; jt++) {
        const int j0 = s * JSPAN + jt * JT;
        // wh tile: 2048 float4, XOR-swizzle d-group by h
#pragma unroll
        for (int l = 0; l < 8; l++) {
            const int idx = t + l * 256;
            const int jj = idx >> 6;
            const int hh = (idx >> 3) & 7;
            const int d4 = idx & 7;
            const float4 v =
                ((const float4*)g_Wh)[(((size_t)b * HH + hh) * NN + j0 + jj) * 8 + d4];
            *(float4*)&wh_s[jj * 256 + hh * 32 + ((d4 ^ hh) & 7) * 4] = v;
        }
        // ed tile transposed [j][h]
        {
            const int hh = t >> 5, jj = t & 31;
            ed_s[jj * 8 + hh] = g_ed[((size_t)b * HH + hh) * NN + j0 + jj];
        }
        __syncthreads();

        unsigned int m0 = ap0[jt];
        unsigned int m1 = ap1[jt];
#pragma unroll 8
        for (int j = 0; j < JT; j++) {
            const float ed = ed_s[j * 8 + h];
            float s0 = ei0 + ed;
            float s1 = ei1 + ed;
            s0 = fmaxf(s0, 0.2f * s0);
            s1 = fmaxf(s1, 0.2f * s1);
            s0 = (m0 & 1u) ? s0 : -12000.f;
            s1 = (m1 & 1u) ? s1 : -12000.f;
            m0 >>= 1; m1 >>= 1;
            const float p0 = ex2(s0);
            const float p1 = ex2(s1);
            den0 += p0;
            den1 += p1;
            const unsigned long long pp0 = packf2(p0);
            const unsigned long long pp1 = packf2(p1);
            const float* wbase = &wh_s[j * 256 + h * 32];
#pragma unroll
            for (int dg = 0; dg < 8; dg++) {
                const ulonglong2 wv = *(const ulonglong2*)&wbase[((dg ^ h) & 7) * 4];
                acc0[dg * 2 + 0] = fma2(pp0, wv.x, acc0[dg * 2 + 0]);
                acc0[dg * 2 + 1] = fma2(pp0, wv.y, acc0[dg * 2 + 1]);
                acc1[dg * 2 + 0] = fma2(pp1, wv.x, acc1[dg * 2 + 0]);
                acc1[dg * 2 + 1] = fma2(pp1, wv.y, acc1[dg * 2 + 1]);
            }
        }
        __syncthreads();
    }

    // write partials: layout [s][b][row][h][d]
    const size_t base0 = ((((size_t)s * BB + b) * NN + row0) * HH + h) * DD;
    const size_t base1 = base0 + HH * DD;
#pragma unroll
    for (int dg = 0; dg < 8; dg++) {
        *(ulonglong2*)&g_part[base0 + dg * 4] = make_ulonglong2(acc0[dg*2], acc0[dg*2+1]);
        *(ulonglong2*)&g_part[base1 + dg * 4] = make_ulonglong2(acc1[dg*2], acc1[dg*2+1]);
    }
    g_den[(((size_t)s * BB + b) * NN + row0) * HH + h] = den0;
    g_den[(((size_t)s * BB + b) * NN + row0 + 1) * HH + h] = den1;
}

// ---------------------------------------------------------------------------
// Kernel 3: combine splits + normalize. 512K float4 elements.
// ---------------------------------------------------------------------------
__global__ __launch_bounds__(256) void k3_reduce(float* __restrict__ out) {
    const int gid = blockIdx.x * 256 + threadIdx.x;     // float4 index, < 512K
    const int d4 = gid & 7;
    const int h  = (gid >> 3) & 7;
    const int i  = (gid >> 6) & (NN - 1);
    const int b  = gid >> 17;

    float4 acc = make_float4(0.f, 0.f, 0.f, 0.f);
    float den = 0.f;
#pragma unroll
    for (int s = 0; s < SPLITS; s++) {
        const size_t pb = ((((size_t)s * BB + b) * NN + i) * HH + h);
        const float4 p = ((const float4*)g_part)[pb * 8 + d4];
        acc.x += p.x; acc.y += p.y; acc.z += p.z; acc.w += p.w;
        den += g_den[pb];
    }
    const float rd = 1.f / den;
    acc.x *= rd; acc.y *= rd; acc.z *= rd; acc.w *= rd;
    ((float4*)out)[gid] = acc;
}

extern "C" void kernel_launch(void* const* d_in, const int* in_sizes, int n_in,
                              void* d_out, int out_size) {
    const float* x   = (const float*)d_in[0];
    const int*   adj = (const int*)d_in[1];
    const float* W   = (const float*)d_in[2];
    const float* a   = (const float*)d_in[3];
    float* out = (float*)d_out;

    cudaFuncSetAttribute(k1_proj, cudaFuncAttributeMaxDynamicSharedMemorySize, 98304);
    cudaFuncSetAttribute(k2_attn, cudaFuncAttributeMaxDynamicSharedMemorySize, 33792);

    k0_pack<<<2048, 256>>>(adj);
    k1_proj<<<dim3(128, 8), 256, 98304>>>(x, W, a);
    k2_attn<<<dim3(32, BB, SPLITS), 256, 33792>>>();
    k3_reduce<<<2048, 256>>>(out);
}

// round 7
// speedup vs baseline: 4.6418x; 2.2738x over previous
#include <cuda_runtime.h>
#include <cstdint>

#define BB 4
#define NN 2048
#define INF 256
#define HH 8
#define DD 32
#define LOG2E 1.44269504f
#define JT 128
#define NTILES (NN / JT)
#define WSTRIDE 40   // wh_s row stride (words): makes B-fragment gather conflict-free

// scratch (allocation-free rule: __device__ globals)
__device__ float g_Wh[BB*HH*NN*DD];            // [b][h][n][d]
__device__ float g_es[BB*HH*NN];               // e_i * log2e
__device__ float g_ed[BB*HH*NN];               // e_j * log2e
__device__ unsigned int g_adjp[BB*NN*(NN/32)]; // packed adj bits

__device__ __forceinline__ float ex2(float x) {
    float r; asm("ex2.approx.ftz.f32 %0, %1;" : "=f"(r) : "f"(x)); return r;
}
__device__ __forceinline__ uint32_t cvt_tf32(float x) {
    uint32_t r; asm("cvt.rna.tf32.f32 %0, %1;" : "=r"(r) : "f"(x)); return r;
}
__device__ __forceinline__ void mma8(float* c, uint32_t a0, uint32_t a1,
                                     uint32_t a2, uint32_t a3,
                                     uint32_t b0, uint32_t b1) {
    asm("mma.sync.aligned.m16n8k8.row.col.f32.tf32.tf32.f32 "
        "{%0,%1,%2,%3}, {%4,%5,%6,%7}, {%8,%9}, {%0,%1,%2,%3};"
        : "+f"(c[0]), "+f"(c[1]), "+f"(c[2]), "+f"(c[3])
        : "r"(a0), "r"(a1), "r"(a2), "r"(a3), "r"(b0), "r"(b1));
}

// ---------------------------------------------------------------------------
// Kernel 0: pack adj -> bitmask
// ---------------------------------------------------------------------------
__global__ __launch_bounds__(256) void k0_pack(const int* __restrict__ adj) {
    const int lane = threadIdx.x & 31;
    const int gw   = blockIdx.x * 8 + (threadIdx.x >> 5);
#pragma unroll 4
    for (int r = 0; r < 32; r++) {
        const size_t u = (size_t)gw * 32 + r;
        const int v = adj[u * 32 + lane];
        const unsigned int bal = __ballot_sync(0xffffffffu, v != 0);
        if (lane == 0) g_adjp[u] = bal;
    }
}

// ---------------------------------------------------------------------------
// Kernel 1: Wh = x @ W, e = Wh·a (pre-scaled by log2e)
// ---------------------------------------------------------------------------
__global__ __launch_bounds__(256) void k1_proj(const float* __restrict__ x,
                                               const float* __restrict__ W,
                                               const float* __restrict__ a) {
    extern __shared__ float sm[];
    float* xs = sm;
    float* Ws = sm + 64 * INF;
    const int h  = blockIdx.y;
    const int b  = blockIdx.x >> 5;
    const int n0 = (blockIdx.x & 31) * 64;
    const int t  = threadIdx.x;

    const float4* xg = (const float4*)(x + ((size_t)b * NN + n0) * INF);
    float4* xs4 = (float4*)xs;
#pragma unroll
    for (int l = 0; l < 16; l++) xs4[t + l * 256] = xg[t + l * 256];
    const float4* wg = (const float4*)(W + (size_t)h * INF * DD);
    float4* ws4 = (float4*)Ws;
#pragma unroll
    for (int l = 0; l < 8; l++) ws4[t + l * 256] = wg[t + l * 256];
    __syncthreads();

    const int d = t & 31;
    const int g = t >> 5;
    float acc[8];
#pragma unroll
    for (int r = 0; r < 8; r++) acc[r] = 0.f;

    for (int kq = 0; kq < INF / 4; kq++) {
        const float w0 = Ws[(kq * 4 + 0) * DD + d];
        const float w1 = Ws[(kq * 4 + 1) * DD + d];
        const float w2 = Ws[(kq * 4 + 2) * DD + d];
        const float w3 = Ws[(kq * 4 + 3) * DD + d];
#pragma unroll
        for (int r = 0; r < 8; r++) {
            const float4 xv = *(const float4*)&xs[(g * 8 + r) * INF + kq * 4];
            acc[r] = fmaf(xv.x, w0, fmaf(xv.y, w1, fmaf(xv.z, w2, fmaf(xv.w, w3, acc[r]))));
        }
    }

    const float asrc = a[h * 2 * DD + d];
    const float adst = a[h * 2 * DD + DD + d];
#pragma unroll
    for (int r = 0; r < 8; r++) {
        const int n = n0 + g * 8 + r;
        g_Wh[(((size_t)b * HH + h) * NN + n) * DD + d] = acc[r];
        float es = acc[r] * asrc;
        float ed = acc[r] * adst;
#pragma unroll
        for (int off = 16; off; off >>= 1) {
            es += __shfl_xor_sync(0xffffffffu, es, off);
            ed += __shfl_xor_sync(0xffffffffu, ed, off);
        }
        if (d == 0) {
            g_es[((size_t)b * HH + h) * NN + n] = es * LOG2E;
            g_ed[((size_t)b * HH + h) * NN + n] = ed * LOG2E;
        }
    }
}

// ---------------------------------------------------------------------------
// Kernel 2: PV on tensor cores via mma.sync tf32 (m16n8k8).
// CTA = (128 i-rows, h, b), 8 warps x 16 rows. D (16x32 per warp) lives in
// 16 regs; P generated directly in A-fragment layout; denom from converted
// tf32 bits so numerator/denominator are consistent.
// ---------------------------------------------------------------------------
__global__ __launch_bounds__(256) void k2_attn(float* __restrict__ out) {
    __shared__ uint32_t wh_s[JT * WSTRIDE];   // tf32-converted Wh tile, 20KB
    __shared__ float    ed_s[JT];
    __shared__ uint4    adjs[JT];

    const int t    = threadIdx.x;
    const int lane = t & 31;
    const int wi   = t >> 5;
    const int l3   = lane & 3;
    const int lq   = lane >> 2;
    const int h  = blockIdx.y;
    const int b  = blockIdx.z;
    const int i0 = blockIdx.x * 128;
    const size_t bh = (size_t)b * HH + h;

    const int r0 = wi * 16 + lq;                  // local row (and +8)
    const float ei0 = g_es[bh * NN + i0 + r0];
    const float ei1 = g_es[bh * NN + i0 + r0 + 8];

    float acc[4][4] = {};
    float den0 = 0.f, den1 = 0.f;

    for (int tile = 0; tile < NTILES; tile++) {
        const int j0 = tile * JT;
        __syncthreads();
        // stage Wh tile, converted to tf32. 1024 float4 loads.
#pragma unroll
        for (int l = 0; l < 4; l++) {
            const int idx = t + l * 256;
            const int jj = idx >> 3, d4 = idx & 7;
            const float4 v = ((const float4*)g_Wh)[(bh * NN + j0 + jj) * 8 + d4];
            uint4 c;
            c.x = cvt_tf32(v.x); c.y = cvt_tf32(v.y);
            c.z = cvt_tf32(v.z); c.w = cvt_tf32(v.w);
            *(uint4*)&wh_s[jj * WSTRIDE + d4 * 4] = c;
        }
        if (t < 128) {
            ed_s[t] = g_ed[bh * NN + j0 + t];
            adjs[t] = *(const uint4*)(g_adjp + ((size_t)b * NN + i0 + t) * (NN / 32) + tile * 4);
        }
        __syncthreads();

        const uint4 wA = adjs[r0];
        const uint4 wB = adjs[r0 + 8];

#pragma unroll
        for (int c = 0; c < 16; c++) {
            const uint32_t mw0 = (c >> 2) == 0 ? wA.x : (c >> 2) == 1 ? wA.y : (c >> 2) == 2 ? wA.z : wA.w;
            const uint32_t mw1 = (c >> 2) == 0 ? wB.x : (c >> 2) == 1 ? wB.y : (c >> 2) == 2 ? wB.z : wB.w;
            const float e0 = ed_s[c * 8 + l3];
            const float e1 = ed_s[c * 8 + 4 + l3];
            float s00 = ei0 + e0, s01 = ei0 + e1;
            float s10 = ei1 + e0, s11 = ei1 + e1;
            s00 = fmaxf(s00, 0.2f * s00);
            s01 = fmaxf(s01, 0.2f * s01);
            s10 = fmaxf(s10, 0.2f * s10);
            s11 = fmaxf(s11, 0.2f * s11);
            const int sh = (c & 3) * 8 + l3;
            s00 = (mw0 >> sh) & 1u ? s00 : -12000.f;
            s01 = (mw0 >> (sh + 4)) & 1u ? s01 : -12000.f;
            s10 = (mw1 >> sh) & 1u ? s10 : -12000.f;
            s11 = (mw1 >> (sh + 4)) & 1u ? s11 : -12000.f;
            // A fragment: a0(row,k), a1(row+8,k), a2(row,k+4), a3(row+8,k+4)
            const uint32_t a0 = cvt_tf32(ex2(s00));
            const uint32_t a1 = cvt_tf32(ex2(s10));
            const uint32_t a2 = cvt_tf32(ex2(s01));
            const uint32_t a3 = cvt_tf32(ex2(s11));
            den0 += __uint_as_float(a0) + __uint_as_float(a2);
            den1 += __uint_as_float(a1) + __uint_as_float(a3);

            const uint32_t* wp = &wh_s[(c * 8 + l3) * WSTRIDE + lq];
#pragma unroll
            for (int nt = 0; nt < 4; nt++) {
                const uint32_t b0 = wp[nt * 8];
                const uint32_t b1 = wp[4 * WSTRIDE + nt * 8];
                mma8(acc[nt], a0, a1, a2, a3, b0, b1);
            }
        }
    }

    // row denominators: reduce over the 4 lanes sharing a row (l3 axis)
    den0 += __shfl_xor_sync(0xffffffffu, den0, 1);
    den0 += __shfl_xor_sync(0xffffffffu, den0, 2);
    den1 += __shfl_xor_sync(0xffffffffu, den1, 1);
    den1 += __shfl_xor_sync(0xffffffffu, den1, 2);
    const float rd0 = 1.f / den0;
    const float rd1 = 1.f / den1;

    float* orow0 = out + ((size_t)b * NN + i0 + r0) * (HH * DD) + h * DD;
    float* orow1 = orow0 + 8 * (HH * DD);
#pragma unroll
    for (int nt = 0; nt < 4; nt++) {
        float2 v0; v0.x = acc[nt][0] * rd0; v0.y = acc[nt][1] * rd0;
        float2 v1; v1.x = acc[nt][2] * rd1; v1.y = acc[nt][3] * rd1;
        *(float2*)&orow0[nt * 8 + 2 * l3] = v0;
        *(float2*)&orow1[nt * 8 + 2 * l3] = v1;
    }
}

extern "C" void kernel_launch(void* const* d_in, const int* in_sizes, int n_in,
                              void* d_out, int out_size) {
    const float* x   = (const float*)d_in[0];
    const int*   adj = (const int*)d_in[1];
    const float* W   = (const float*)d_in[2];
    const float* a   = (const float*)d_in[3];
    float* out = (float*)d_out;

    cudaFuncSetAttribute(k1_proj, cudaFuncAttributeMaxDynamicSharedMemorySize, 98304);

    k0_pack<<<2048, 256>>>(adj);
    k1_proj<<<dim3(128, 8), 256, 98304>>>(x, W, a);
    k2_attn<<<dim3(16, HH, BB), 256>>>(out);
}

// round 9
// speedup vs baseline: 5.1806x; 1.1161x over previous
#include <cuda_runtime.h>
#include <cstdint>

#define BB 4
#define NN 2048
#define INF 256
#define HH 8
#define DD 32
#define LOG2E 1.44269504f
#define JT 128
#define NTILES (NN / JT)
#define WSTRIDE 40   // wh_s row stride (words): conflict-free LDS.128 B-frag fetch

// scratch (allocation-free rule: __device__ globals)
__device__ float g_Wh[BB*HH*NN*DD];            // [b][h][n][d]
__device__ float g_es[BB*HH*NN];               // e_i * log2e
__device__ float g_ed[BB*HH*NN];               // e_j * log2e, PAIRED layout per 128-group
__device__ unsigned int g_adjp[BB*NN*(NN/32)]; // packed adj bits, interleaved layout

__device__ __forceinline__ float ex2(float x) {
    float r; asm("ex2.approx.ftz.f32 %0, %1;" : "=f"(r) : "f"(x)); return r;
}
__device__ __forceinline__ uint32_t cvt_tf32(float x) {
    uint32_t r; asm("cvt.rna.tf32.f32 %0, %1;" : "=r"(r) : "f"(x)); return r;
}
__device__ __forceinline__ void mma8(float* c, uint32_t a0, uint32_t a1,
                                     uint32_t a2, uint32_t a3,
                                     uint32_t b0, uint32_t b1) {
    asm("mma.sync.aligned.m16n8k8.row.col.f32.tf32.tf32.f32 "
        "{%0,%1,%2,%3}, {%4,%5,%6,%7}, {%8,%9}, {%0,%1,%2,%3};"
        : "+f"(c[0]), "+f"(c[1]), "+f"(c[2]), "+f"(c[3])
        : "r"(a0), "r"(a1), "r"(a2), "r"(a3), "r"(b0), "r"(b1));
}

// ---------------------------------------------------------------------------
// Kernel 0: pack adj -> interleaved bitmask.
// Per 128-j group g: word g*4 + (j&3), bit (j>>2)&31. One warp per row.
// grid 1024 x 256 (8192 warps = B*N rows).
// ---------------------------------------------------------------------------
__global__ __launch_bounds__(256) void k0_pack(const int* __restrict__ adj) {
    const int lane = threadIdx.x & 31;
    const int row  = blockIdx.x * 8 + (threadIdx.x >> 5);   // 0..8191
    const int4* src = (const int4*)(adj + (size_t)row * NN) + lane;
    unsigned int* dst = g_adjp + (size_t)row * (NN / 32);
#pragma unroll 4
    for (int g = 0; g < 16; g++) {
        const int4 v = src[g * 32];
        const unsigned int b0 = __ballot_sync(0xffffffffu, v.x != 0);
        const unsigned int b1 = __ballot_sync(0xffffffffu, v.y != 0);
        const unsigned int b2 = __ballot_sync(0xffffffffu, v.z != 0);
        const unsigned int b3 = __ballot_sync(0xffffffffu, v.w != 0);
        if (lane == 0) *(uint4*)(dst + g * 4) = make_uint4(b0, b1, b2, b3);
    }
}

// ---------------------------------------------------------------------------
// Kernel 1: Wh = x @ W, e = Wh·a (pre-scaled by log2e). ed stored PAIRED:
// within each 128-group, index = c*8 + (n&3)*2 + ((n>>2)&1), c = (n>>3)&15.
// ---------------------------------------------------------------------------
__global__ __launch_bounds__(256) void k1_proj(const float* __restrict__ x,
                                               const float* __restrict__ W,
                                               const float* __restrict__ a) {
    extern __shared__ float sm[];
    float* xs = sm;
    float* Ws = sm + 64 * INF;
    const int h  = blockIdx.y;
    const int b  = blockIdx.x >> 5;
    const int n0 = (blockIdx.x & 31) * 64;
    const int t  = threadIdx.x;

    const float4* xg = (const float4*)(x + ((size_t)b * NN + n0) * INF);
    float4* xs4 = (float4*)xs;
#pragma unroll
    for (int l = 0; l < 16; l++) xs4[t + l * 256] = xg[t + l * 256];
    const float4* wg = (const float4*)(W + (size_t)h * INF * DD);
    float4* ws4 = (float4*)Ws;
#pragma unroll
    for (int l = 0; l < 8; l++) ws4[t + l * 256] = wg[t + l * 256];
    __syncthreads();

    const int d = t & 31;
    const int g = t >> 5;
    float acc[8];
#pragma unroll
    for (int r = 0; r < 8; r++) acc[r] = 0.f;

    for (int kq = 0; kq < INF / 4; kq++) {
        const float w0 = Ws[(kq * 4 + 0) * DD + d];
        const float w1 = Ws[(kq * 4 + 1) * DD + d];
        const float w2 = Ws[(kq * 4 + 2) * DD + d];
        const float w3 = Ws[(kq * 4 + 3) * DD + d];
#pragma unroll
        for (int r = 0; r < 8; r++) {
            const float4 xv = *(const float4*)&xs[(g * 8 + r) * INF + kq * 4];
            acc[r] = fmaf(xv.x, w0, fmaf(xv.y, w1, fmaf(xv.z, w2, fmaf(xv.w, w3, acc[r]))));
        }
    }

    const float asrc = a[h * 2 * DD + d];
    const float adst = a[h * 2 * DD + DD + d];
#pragma unroll
    for (int r = 0; r < 8; r++) {
        const int n = n0 + g * 8 + r;
        g_Wh[(((size_t)b * HH + h) * NN + n) * DD + d] = acc[r];
        float es = acc[r] * asrc;
        float ed = acc[r] * adst;
#pragma unroll
        for (int off = 16; off; off >>= 1) {
            es += __shfl_xor_sync(0xffffffffu, es, off);
            ed += __shfl_xor_sync(0xffffffffu, ed, off);
        }
        if (d == 0) {
            g_es[((size_t)b * HH + h) * NN + n] = es * LOG2E;
            const int np = (n & ~127) | (((n >> 3) & 15) * 8 + (n & 3) * 2 + ((n >> 2) & 1));
            g_ed[((size_t)b * HH + h) * NN + np] = ed * LOG2E;
        }
    }
}

// ---------------------------------------------------------------------------
// Kernel 2: PV on tensor cores, mma.sync tf32 m16n8k8.
// CTA = (64 i-rows, h, b), 128 thr / 4 warps, each warp 16 rows. Single wave.
// Per c: 1 LDS.64 (ed pair) + const-shift mask + 4 ex2/cvt + 2 LDS.128 (B) + 4 MMA.
// ---------------------------------------------------------------------------
__global__ __launch_bounds__(128) void k2_attn(float* __restrict__ out) {
    __shared__ uint32_t wh_s[JT * WSTRIDE];   // tf32 Wh tile, perm(d)=(d&7)*4+(d>>3)
    __shared__ float    ed_s[JT];             // paired layout

    const int t    = threadIdx.x;
    const int lane = t & 31;
    const int wi   = t >> 5;                  // 0..3
    const int l3   = lane & 3;
    const int lq   = lane >> 2;
    const int h  = blockIdx.y;
    const int b  = blockIdx.z;
    const int i0 = blockIdx.x * 64;
    const size_t bh = (size_t)b * HH + h;

    const int r0 = wi * 16 + lq;              // local row (and +8)
    const float ei0 = g_es[bh * NN + i0 + r0];
    const float ei1 = g_es[bh * NN + i0 + r0 + 8];
    const unsigned int* ap0 = g_adjp + ((size_t)b * NN + i0 + r0) * (NN / 32) + l3;
    const unsigned int* ap1 = ap0 + 8 * (NN / 32);

    float acc[4][4] = {};
    float den0 = 0.f, den1 = 0.f;

    for (int tile = 0; tile < NTILES; tile++) {
        const int j0 = tile * JT;
        __syncthreads();
        // stage Wh tile (tf32, permuted columns): 8 float4 per thread
#pragma unroll
        for (int l = 0; l < 8; l++) {
            const int idx = t + l * 128;
            const int jj = idx >> 3, d4 = idx & 7;
            const float4 v = ((const float4*)g_Wh)[(bh * NN + j0 + jj) * 8 + d4];
            uint32_t* wb = &wh_s[jj * WSTRIDE + (d4 & 1) * 16 + (d4 >> 1)];
            wb[0]  = cvt_tf32(v.x);
            wb[4]  = cvt_tf32(v.y);
            wb[8]  = cvt_tf32(v.z);
            wb[12] = cvt_tf32(v.w);
        }
        ed_s[t] = g_ed[bh * NN + j0 + t];
        const unsigned int w0 = ap0[tile * 4];
        const unsigned int w1 = ap1[tile * 4];
        __syncthreads();

#pragma unroll
        for (int c = 0; c < 16; c++) {
            const float2 e = *(const float2*)&ed_s[c * 8 + l3 * 2];
            float s00 = ei0 + e.x, s01 = ei0 + e.y;
            float s10 = ei1 + e.x, s11 = ei1 + e.y;
            s00 = fmaxf(s00, 0.2f * s00);
            s01 = fmaxf(s01, 0.2f * s01);
            s10 = fmaxf(s10, 0.2f * s10);
            s11 = fmaxf(s11, 0.2f * s11);
            s00 = (w0 & (1u << (2 * c))) ? s00 : -12000.f;
            s01 = (w0 & (2u << (2 * c))) ? s01 : -12000.f;
            s10 = (w1 & (1u << (2 * c))) ? s10 : -12000.f;
            s11 = (w1 & (2u << (2 * c))) ? s11 : -12000.f;
            const uint32_t a0 = cvt_tf32(ex2(s00));
            const uint32_t a2 = cvt_tf32(ex2(s01));
            const uint32_t a1 = cvt_tf32(ex2(s10));
            const uint32_t a3 = cvt_tf32(ex2(s11));
            den0 += __uint_as_float(a0) + __uint_as_float(a2);
            den1 += __uint_as_float(a1) + __uint_as_float(a3);

            const uint32_t* wp = &wh_s[(c * 8 + l3) * WSTRIDE + lq * 4];
            const uint4 B0 = *(const uint4*)wp;                  // b0 for nt=0..3
            const uint4 B1 = *(const uint4*)(wp + 4 * WSTRIDE);  // b1 for nt=0..3
            mma8(acc[0], a0, a1, a2, a3, B0.x, B1.x);
            mma8(acc[1], a0, a1, a2, a3, B0.y, B1.y);
            mma8(acc[2], a0, a1, a2, a3, B0.z, B1.z);
            mma8(acc[3], a0, a1, a2, a3, B0.w, B1.w);
        }
    }

    den0 += __shfl_xor_sync(0xffffffffu, den0, 1);
    den0 += __shfl_xor_sync(0xffffffffu, den0, 2);
    den1 += __shfl_xor_sync(0xffffffffu, den1, 1);
    den1 += __shfl_xor_sync(0xffffffffu, den1, 2);
    const float rd0 = 1.f / den0;
    const float rd1 = 1.f / den1;

    float* orow0 = out + ((size_t)b * NN + i0 + r0) * (HH * DD) + h * DD;
    float* orow1 = orow0 + 8 * (HH * DD);
#pragma unroll
    for (int nt = 0; nt < 4; nt++) {
        float2 v0; v0.x = acc[nt][0] * rd0; v0.y = acc[nt][1] * rd0;
        float2 v1; v1.x = acc[nt][2] * rd1; v1.y = acc[nt][3] * rd1;
        *(float2*)&orow0[nt * 8 + 2 * l3] = v0;
        *(float2*)&orow1[nt * 8 + 2 * l3] = v1;
    }
}

extern "C" void kernel_launch(void* const* d_in, const int* in_sizes, int n_in,
                              void* d_out, int out_size) {
    const float* x   = (const float*)d_in[0];
    const int*   adj = (const int*)d_in[1];
    const float* W   = (const float*)d_in[2];
    const float* a   = (const float*)d_in[3];
    float* out = (float*)d_out;

    cudaFuncSetAttribute(k1_proj, cudaFuncAttributeMaxDynamicSharedMemorySize, 98304);

    k0_pack<<<1024, 256>>>(adj);
    k1_proj<<<dim3(128, 8), 256, 98304>>>(x, W, a);
    k2_attn<<<dim3(32, HH, BB), 128>>>(out);
}

// round 10
// speedup vs baseline: 5.5211x; 1.0657x over previous
#include <cuda_runtime.h>
#include <cstdint>

#define BB 4
#define NN 2048
#define INF 256
#define HH 8
#define DD 32
#define LOG2E 1.44269504f
#define JT 128
#define NTILES (NN / JT)
#define WSTRIDE 40   // padded row stride (words): conflict-free LDS.128 B-frag fetch

// scratch (allocation-free rule: __device__ globals)
__device__ float g_Wh[BB*HH*NN*DD];            // [b][h][n][d]
__device__ float g_es[BB*HH*NN];               // e_i * log2e
__device__ float g_ed[BB*HH*NN];               // e_j * log2e, PAIRED per 128-group
__device__ unsigned int g_adjp[BB*NN*(NN/32)]; // packed adj bits, interleaved layout

__device__ __forceinline__ float ex2(float x) {
    float r; asm("ex2.approx.ftz.f32 %0, %1;" : "=f"(r) : "f"(x)); return r;
}
__device__ __forceinline__ uint32_t cvt_tf32(float x) {
    uint32_t r; asm("cvt.rna.tf32.f32 %0, %1;" : "=r"(r) : "f"(x)); return r;
}
__device__ __forceinline__ uint32_t smem_u32(const void* p) {
    uint32_t a;
    asm("{ .reg .u64 t; cvta.to.shared.u64 t, %1; cvt.u32.u64 %0, t; }" : "=r"(a) : "l"(p));
    return a;
}
__device__ __forceinline__ void cp16(uint32_t dst, const void* src) {
    asm volatile("cp.async.cg.shared.global [%0], [%1], 16;" :: "r"(dst), "l"(src));
}
#define CP_COMMIT() asm volatile("cp.async.commit_group;" ::: "memory")
#define CP_WAIT(n)  asm volatile("cp.async.wait_group %0;" :: "n"(n) : "memory")

__device__ __forceinline__ void mma8(float* c, uint32_t a0, uint32_t a1,
                                     uint32_t a2, uint32_t a3,
                                     uint32_t b0, uint32_t b1) {
    asm("mma.sync.aligned.m16n8k8.row.col.f32.tf32.tf32.f32 "
        "{%0,%1,%2,%3}, {%4,%5,%6,%7}, {%8,%9}, {%0,%1,%2,%3};"
        : "+f"(c[0]), "+f"(c[1]), "+f"(c[2]), "+f"(c[3])
        : "r"(a0), "r"(a1), "r"(a2), "r"(a3), "r"(b0), "r"(b1));
}

// ---------------------------------------------------------------------------
// Kernel 0: pack adj -> interleaved bitmask. MLP-8 batched loads.
// Per 128-j group g: word g*4 + (j&3), bit (j>>2)&31. One warp per row.
// ---------------------------------------------------------------------------
__global__ __launch_bounds__(256) void k0_pack(const int* __restrict__ adj) {
    const int lane = threadIdx.x & 31;
    const int row  = blockIdx.x * 8 + (threadIdx.x >> 5);   // 0..8191
    const int4* src = (const int4*)(adj + (size_t)row * NN) + lane;
    unsigned int* dst = g_adjp + (size_t)row * (NN / 32);
#pragma unroll
    for (int g = 0; g < 16; g += 4) {
        int4 v[4];
#pragma unroll
        for (int q = 0; q < 4; q++) v[q] = src[(g + q) * 32];
#pragma unroll
        for (int q = 0; q < 4; q++) {
            const unsigned int b0 = __ballot_sync(0xffffffffu, v[q].x != 0);
            const unsigned int b1 = __ballot_sync(0xffffffffu, v[q].y != 0);
            const unsigned int b2 = __ballot_sync(0xffffffffu, v[q].z != 0);
            const unsigned int b3 = __ballot_sync(0xffffffffu, v[q].w != 0);
            if (lane == 0) *(uint4*)(dst + (g + q) * 4) = make_uint4(b0, b1, b2, b3);
        }
    }
}

// ---------------------------------------------------------------------------
// Kernel 1: Wh = x @ W, e = Wh·a (pre-scaled by log2e). ed stored PAIRED:
// within each 128-group, index = c*8 + (n&3)*2 + ((n>>2)&1), c = (n>>3)&15.
// ---------------------------------------------------------------------------
__global__ __launch_bounds__(256) void k1_proj(const float* __restrict__ x,
                                               const float* __restrict__ W,
                                               const float* __restrict__ a) {
    extern __shared__ float sm[];
    float* xs = sm;
    float* Ws = sm + 64 * INF;
    const int h  = blockIdx.y;
    const int b  = blockIdx.x >> 5;
    const int n0 = (blockIdx.x & 31) * 64;
    const int t  = threadIdx.x;

    const float4* xg = (const float4*)(x + ((size_t)b * NN + n0) * INF);
    float4* xs4 = (float4*)xs;
#pragma unroll
    for (int l = 0; l < 16; l++) xs4[t + l * 256] = xg[t + l * 256];
    const float4* wg = (const float4*)(W + (size_t)h * INF * DD);
    float4* ws4 = (float4*)Ws;
#pragma unroll
    for (int l = 0; l < 8; l++) ws4[t + l * 256] = wg[t + l * 256];
    __syncthreads();

    const int d = t & 31;
    const int g = t >> 5;
    float acc[8];
#pragma unroll
    for (int r = 0; r < 8; r++) acc[r] = 0.f;

    for (int kq = 0; kq < INF / 4; kq++) {
        const float w0 = Ws[(kq * 4 + 0) * DD + d];
        const float w1 = Ws[(kq * 4 + 1) * DD + d];
        const float w2 = Ws[(kq * 4 + 2) * DD + d];
        const float w3 = Ws[(kq * 4 + 3) * DD + d];
#pragma unroll
        for (int r = 0; r < 8; r++) {
            const float4 xv = *(const float4*)&xs[(g * 8 + r) * INF + kq * 4];
            acc[r] = fmaf(xv.x, w0, fmaf(xv.y, w1, fmaf(xv.z, w2, fmaf(xv.w, w3, acc[r]))));
        }
    }

    const float asrc = a[h * 2 * DD + d];
    const float adst = a[h * 2 * DD + DD + d];
#pragma unroll
    for (int r = 0; r < 8; r++) {
        const int n = n0 + g * 8 + r;
        g_Wh[(((size_t)b * HH + h) * NN + n) * DD + d] = acc[r];
        float es = acc[r] * asrc;
        float ed = acc[r] * adst;
#pragma unroll
        for (int off = 16; off; off >>= 1) {
            es += __shfl_xor_sync(0xffffffffu, es, off);
            ed += __shfl_xor_sync(0xffffffffu, ed, off);
        }
        if (d == 0) {
            g_es[((size_t)b * HH + h) * NN + n] = es * LOG2E;
            const int np = (n & ~127) | (((n >> 3) & 15) * 8 + (n & 3) * 2 + ((n >> 2) & 1));
            g_ed[((size_t)b * HH + h) * NN + np] = ed * LOG2E;
        }
    }
}

// ---------------------------------------------------------------------------
// Kernel 2: PV on tensor cores, mma.sync tf32 m16n8k8, cp.async double-buffer.
// CTA = (64 i-rows, h, b), 128 thr / 4 warps. B operand = raw fp32 bits
// (HW truncates to tf32). nt maps to d = 4*lq + nt.
// ---------------------------------------------------------------------------
__global__ __launch_bounds__(128) void k2_attn(float* __restrict__ out) {
    __shared__ float wh_s[2][JT * WSTRIDE];   // raw fp32 Wh tiles, 2 x 20KB
    __shared__ float ed_s[2][JT];             // paired layout

    const int t    = threadIdx.x;
    const int lane = t & 31;
    const int wi   = t >> 5;                  // 0..3
    const int l3   = lane & 3;
    const int lq   = lane >> 2;
    const int h  = blockIdx.y;
    const int b  = blockIdx.z;
    const int i0 = blockIdx.x * 64;
    const size_t bh = (size_t)b * HH + h;

    const int r0 = wi * 16 + lq;              // local row (and +8)
    const float ei0 = g_es[bh * NN + i0 + r0];
    const float ei1 = g_es[bh * NN + i0 + r0 + 8];
    const unsigned int* ap0 = g_adjp + ((size_t)b * NN + i0 + r0) * (NN / 32) + l3;
    const unsigned int* ap1 = ap0 + 8 * (NN / 32);

    const uint32_t wh_sb = smem_u32(wh_s);
    const uint32_t ed_sb = smem_u32(ed_s);
    const float4* whsrc0 = (const float4*)g_Wh + bh * NN * 8;
    const float4* edsrc0 = (const float4*)(g_ed + bh * NN);

    float acc[4][4] = {};
    float den0 = 0.f, den1 = 0.f;

    // stage tile 0
    {
        const uint32_t wdst = wh_sb;
#pragma unroll
        for (int l = 0; l < 8; l++) {
            const int idx = t + l * 128;
            const int jj = idx >> 3, d4 = idx & 7;
            cp16(wdst + jj * (WSTRIDE * 4) + d4 * 16, whsrc0 + jj * 8 + d4);
        }
        if (t < 32) cp16(ed_sb + t * 16, edsrc0 + t);
        CP_COMMIT();
    }
    unsigned int w0n = ap0[0], w1n = ap1[0];

    for (int tile = 0; tile < NTILES; tile++) {
        const int cur = tile & 1;
        const unsigned int w0 = w0n, w1 = w1n;
        if (tile) __syncthreads();            // all warps done with buf[cur] (as prev dst)
        if (tile + 1 < NTILES) {
            const int nxt = (tile + 1) & 1;
            const uint32_t wdst = wh_sb + nxt * (JT * WSTRIDE * 4);
            const float4* wsrc = whsrc0 + (size_t)(tile + 1) * JT * 8;
#pragma unroll
            for (int l = 0; l < 8; l++) {
                const int idx = t + l * 128;
                const int jj = idx >> 3, d4 = idx & 7;
                cp16(wdst + jj * (WSTRIDE * 4) + d4 * 16, wsrc + jj * 8 + d4);
            }
            if (t < 32) cp16(ed_sb + nxt * 512 + t * 16,
                             edsrc0 + (size_t)(tile + 1) * (JT / 4) + t);
            CP_COMMIT();
            w0n = ap0[(tile + 1) * 4];
            w1n = ap1[(tile + 1) * 4];
            CP_WAIT(1);
        } else {
            CP_WAIT(0);
        }
        __syncthreads();

        const float* edp = ed_s[cur];
        const uint32_t* whp = (const uint32_t*)wh_s[cur];

#pragma unroll
        for (int c = 0; c < 16; c++) {
            const float2 e = *(const float2*)&edp[c * 8 + l3 * 2];
            float s00 = ei0 + e.x, s01 = ei0 + e.y;
            float s10 = ei1 + e.x, s11 = ei1 + e.y;
            s00 = fmaxf(s00, 0.2f * s00);
            s01 = fmaxf(s01, 0.2f * s01);
            s10 = fmaxf(s10, 0.2f * s10);
            s11 = fmaxf(s11, 0.2f * s11);
            s00 = (w0 & (1u << (2 * c))) ? s00 : -12000.f;
            s01 = (w0 & (2u << (2 * c))) ? s01 : -12000.f;
            s10 = (w1 & (1u << (2 * c))) ? s10 : -12000.f;
            s11 = (w1 & (2u << (2 * c))) ? s11 : -12000.f;
            const uint32_t a0 = cvt_tf32(ex2(s00));
            const uint32_t a2 = cvt_tf32(ex2(s01));
            const uint32_t a1 = cvt_tf32(ex2(s10));
            const uint32_t a3 = cvt_tf32(ex2(s11));
            den0 += __uint_as_float(a0) + __uint_as_float(a2);
            den1 += __uint_as_float(a1) + __uint_as_float(a3);

            const uint32_t* wp = whp + (c * 8 + l3) * WSTRIDE + lq * 4;
            const uint4 B0 = *(const uint4*)wp;                  // k=l3,   nt=0..3 (d=4lq+nt)
            const uint4 B1 = *(const uint4*)(wp + 4 * WSTRIDE);  // k=l3+4, nt=0..3
            mma8(acc[0], a0, a1, a2, a3, B0.x, B1.x);
            mma8(acc[1], a0, a1, a2, a3, B0.y, B1.y);
            mma8(acc[2], a0, a1, a2, a3, B0.z, B1.z);
            mma8(acc[3], a0, a1, a2, a3, B0.w, B1.w);
        }
    }

    den0 += __shfl_xor_sync(0xffffffffu, den0, 1);
    den0 += __shfl_xor_sync(0xffffffffu, den0, 2);
    den1 += __shfl_xor_sync(0xffffffffu, den1, 1);
    den1 += __shfl_xor_sync(0xffffffffu, den1, 2);
    const float rd0 = 1.f / den0;
    const float rd1 = 1.f / den1;

    // output cols: c{0,1} -> d = 8*l3 + nt, 8*l3+4+nt  => two float4 per row
    float* orow0 = out + ((size_t)b * NN + i0 + r0) * (HH * DD) + h * DD + 8 * l3;
    float* orow1 = orow0 + 8 * (HH * DD);
    float4 v;
    v.x = acc[0][0] * rd0; v.y = acc[1][0] * rd0; v.z = acc[2][0] * rd0; v.w = acc[3][0] * rd0;
    *(float4*)orow0 = v;
    v.x = acc[0][1] * rd0; v.y = acc[1][1] * rd0; v.z = acc[2][1] * rd0; v.w = acc[3][1] * rd0;
    *(float4*)(orow0 + 4) = v;
    v.x = acc[0][2] * rd1; v.y = acc[1][2] * rd1; v.z = acc[2][2] * rd1; v.w = acc[3][2] * rd1;
    *(float4*)orow1 = v;
    v.x = acc[0][3] * rd1; v.y = acc[1][3] * rd1; v.z = acc[2][3] * rd1; v.w = acc[3][3] * rd1;
    *(float4*)(orow1 + 4) = v;
}

extern "C" void kernel_launch(void* const* d_in, const int* in_sizes, int n_in,
                              void* d_out, int out_size) {
    const float* x   = (const float*)d_in[0];
    const int*   adj = (const int*)d_in[1];
    const float* W   = (const float*)d_in[2];
    const float* a   = (const float*)d_in[3];
    float* out = (float*)d_out;

    cudaFuncSetAttribute(k1_proj, cudaFuncAttributeMaxDynamicSharedMemorySize, 98304);

    k0_pack<<<1024, 256>>>(adj);
    k1_proj<<<dim3(128, 8), 256, 98304>>>(x, W, a);
    k2_attn<<<dim3(32, HH, BB), 128>>>(out);
}

// round 11
// speedup vs baseline: 5.5390x; 1.0032x over previous
#include <cuda_runtime.h>
#include <cstdint>

#define BB 4
#define NN 2048
#define INF 256
#define HH 8
#define DD 32
#define LOG2E 1.44269504f
#define HT 64                 // half-tile rows
#define WSTRIDE 40            // padded row stride (words): conflict-free LDS.128

// scratch (allocation-free rule: __device__ globals)
__device__ float g_Wh[BB*HH*NN*DD];            // [b][h][n][d]
__device__ float g_es[BB*HH*NN];               // e_i * log2e
__device__ float g_ed[BB*HH*NN];               // e_j * log2e, PAIRED per 128-group
__device__ unsigned int g_adjp[BB*NN*(NN/32)]; // packed adj bits, interleaved layout

__device__ __forceinline__ float ex2(float x) {
    float r; asm("ex2.approx.ftz.f32 %0, %1;" : "=f"(r) : "f"(x)); return r;
}
__device__ __forceinline__ uint32_t smem_u32(const void* p) {
    uint32_t a;
    asm("{ .reg .u64 t; cvta.to.shared.u64 t, %1; cvt.u32.u64 %0, t; }" : "=r"(a) : "l"(p));
    return a;
}
__device__ __forceinline__ void cp16(uint32_t dst, const void* src) {
    asm volatile("cp.async.cg.shared.global [%0], [%1], 16;" :: "r"(dst), "l"(src));
}
#define CP_COMMIT() asm volatile("cp.async.commit_group;" ::: "memory")
#define CP_WAIT(n)  asm volatile("cp.async.wait_group %0;" :: "n"(n) : "memory")

__device__ __forceinline__ void mma8(float* c, uint32_t a0, uint32_t a1,
                                     uint32_t a2, uint32_t a3,
                                     uint32_t b0, uint32_t b1) {
    asm("mma.sync.aligned.m16n8k8.row.col.f32.tf32.tf32.f32 "
        "{%0,%1,%2,%3}, {%4,%5,%6,%7}, {%8,%9}, {%0,%1,%2,%3};"
        : "+f"(c[0]), "+f"(c[1]), "+f"(c[2]), "+f"(c[3])
        : "r"(a0), "r"(a1), "r"(a2), "r"(a3), "r"(b0), "r"(b1));
}

// ---------------------------------------------------------------------------
// Kernel 0: pack adj -> interleaved bitmask. MLP-8 batched loads.
// Per 128-j group g: word g*4 + (j&3), bit (j>>2)&31. One warp per row.
// ---------------------------------------------------------------------------
__global__ __launch_bounds__(256) void k0_pack(const int* __restrict__ adj) {
    const int lane = threadIdx.x & 31;
    const int row  = blockIdx.x * 8 + (threadIdx.x >> 5);   // 0..8191
    const int4* src = (const int4*)(adj + (size_t)row * NN) + lane;
    unsigned int* dst = g_adjp + (size_t)row * (NN / 32);
#pragma unroll
    for (int g = 0; g < 16; g += 8) {
        int4 v[8];
#pragma unroll
        for (int q = 0; q < 8; q++) v[q] = src[(g + q) * 32];
#pragma unroll
        for (int q = 0; q < 8; q++) {
            const unsigned int b0 = __ballot_sync(0xffffffffu, v[q].x != 0);
            const unsigned int b1 = __ballot_sync(0xffffffffu, v[q].y != 0);
            const unsigned int b2 = __ballot_sync(0xffffffffu, v[q].z != 0);
            const unsigned int b3 = __ballot_sync(0xffffffffu, v[q].w != 0);
            if (lane == 0) *(uint4*)(dst + (g + q) * 4) = make_uint4(b0, b1, b2, b3);
        }
    }
}

// ---------------------------------------------------------------------------
// Kernel 1: Wh = x @ W, e = Wh·a (pre-scaled by log2e). ed stored PAIRED:
// within each 128-group, index = c*8 + (n&3)*2 + ((n>>2)&1), c = (n>>3)&15.
// ---------------------------------------------------------------------------
__global__ __launch_bounds__(256) void k1_proj(const float* __restrict__ x,
                                               const float* __restrict__ W,
                                               const float* __restrict__ a) {
    extern __shared__ float sm[];
    float* xs = sm;
    float* Ws = sm + 64 * INF;
    const int h  = blockIdx.y;
    const int b  = blockIdx.x >> 5;
    const int n0 = (blockIdx.x & 31) * 64;
    const int t  = threadIdx.x;

    const float4* xg = (const float4*)(x + ((size_t)b * NN + n0) * INF);
    float4* xs4 = (float4*)xs;
#pragma unroll
    for (int l = 0; l < 16; l++) xs4[t + l * 256] = xg[t + l * 256];
    const float4* wg = (const float4*)(W + (size_t)h * INF * DD);
    float4* ws4 = (float4*)Ws;
#pragma unroll
    for (int l = 0; l < 8; l++) ws4[t + l * 256] = wg[t + l * 256];
    __syncthreads();

    const int d = t & 31;
    const int g = t >> 5;
    float acc[8];
#pragma unroll
    for (int r = 0; r < 8; r++) acc[r] = 0.f;

    for (int kq = 0; kq < INF / 4; kq++) {
        const float w0 = Ws[(kq * 4 + 0) * DD + d];
        const float w1 = Ws[(kq * 4 + 1) * DD + d];
        const float w2 = Ws[(kq * 4 + 2) * DD + d];
        const float w3 = Ws[(kq * 4 + 3) * DD + d];
#pragma unroll
        for (int r = 0; r < 8; r++) {
            const float4 xv = *(const float4*)&xs[(g * 8 + r) * INF + kq * 4];
            acc[r] = fmaf(xv.x, w0, fmaf(xv.y, w1, fmaf(xv.z, w2, fmaf(xv.w, w3, acc[r]))));
        }
    }

    const float asrc = a[h * 2 * DD + d];
    const float adst = a[h * 2 * DD + DD + d];
#pragma unroll
    for (int r = 0; r < 8; r++) {
        const int n = n0 + g * 8 + r;
        g_Wh[(((size_t)b * HH + h) * NN + n) * DD + d] = acc[r];
        float es = acc[r] * asrc;
        float ed = acc[r] * adst;
#pragma unroll
        for (int off = 16; off; off >>= 1) {
            es += __shfl_xor_sync(0xffffffffu, es, off);
            ed += __shfl_xor_sync(0xffffffffu, ed, off);
        }
        if (d == 0) {
            g_es[((size_t)b * HH + h) * NN + n] = es * LOG2E;
            const int np = (n & ~127) | (((n >> 3) & 15) * 8 + (n & 3) * 2 + ((n >> 2) & 1));
            g_ed[((size_t)b * HH + h) * NN + np] = ed * LOG2E;
        }
    }
}

// ---------------------------------------------------------------------------
// Kernel 2: PV via mma.sync tf32 m16n8k8, half-tile (64j) double-buffered
// cp.async. A operand = raw ex2 bits (HW truncates to tf32); denominator
// sums the identically truncated values. 21KB smem, 7 CTAs/SM, single wave.
// ---------------------------------------------------------------------------
#define COMPUTE_HALF(CB, whp, edp, w0, w1)                                    \
    _Pragma("unroll")                                                         \
    for (int c = 0; c < 8; c++) {                                             \
        const float2 e = *(const float2*)&(edp)[c * 8 + l3 * 2];              \
        float s00 = ei0 + e.x, s01 = ei0 + e.y;                               \
        float s10 = ei1 + e.x, s11 = ei1 + e.y;                               \
        s00 = fmaxf(s00, 0.2f * s00);                                         \
        s01 = fmaxf(s01, 0.2f * s01);                                         \
        s10 = fmaxf(s10, 0.2f * s10);                                         \
        s11 = fmaxf(s11, 0.2f * s11);                                         \
        s00 = ((w0) & (1u << (2 * ((CB) + c)))) ? s00 : -12000.f;             \
        s01 = ((w0) & (2u << (2 * ((CB) + c)))) ? s01 : -12000.f;             \
        s10 = ((w1) & (1u << (2 * ((CB) + c)))) ? s10 : -12000.f;             \
        s11 = ((w1) & (2u << (2 * ((CB) + c)))) ? s11 : -12000.f;             \
        const uint32_t a0 = __float_as_uint(ex2(s00));                        \
        const uint32_t a2 = __float_as_uint(ex2(s01));                        \
        const uint32_t a1 = __float_as_uint(ex2(s10));                        \
        const uint32_t a3 = __float_as_uint(ex2(s11));                        \
        den0 += __uint_as_float(a0 & 0xffffe000u) + __uint_as_float(a2 & 0xffffe000u); \
        den1 += __uint_as_float(a1 & 0xffffe000u) + __uint_as_float(a3 & 0xffffe000u); \
        const uint32_t* wp = (whp) + (c * 8 + l3) * WSTRIDE + lq * 4;         \
        const uint4 B0 = *(const uint4*)wp;                                   \
        const uint4 B1 = *(const uint4*)(wp + 4 * WSTRIDE);                   \
        mma8(acc[0], a0, a1, a2, a3, B0.x, B1.x);                             \
        mma8(acc[1], a0, a1, a2, a3, B0.y, B1.y);                             \
        mma8(acc[2], a0, a1, a2, a3, B0.z, B1.z);                             \
        mma8(acc[3], a0, a1, a2, a3, B0.w, B1.w);                             \
    }

__global__ __launch_bounds__(128, 7) void k2_attn(float* __restrict__ out) {
    __shared__ float wh_s[2][HT * WSTRIDE];   // raw fp32 Wh half-tiles, 2 x 10KB
    __shared__ float ed_s[2][HT];             // paired layout halves

    const int t    = threadIdx.x;
    const int lane = t & 31;
    const int wi   = t >> 5;                  // 0..3
    const int l3   = lane & 3;
    const int lq   = lane >> 2;
    const int h  = blockIdx.y;
    const int b  = blockIdx.z;
    const int i0 = blockIdx.x * 64;
    const size_t bh = (size_t)b * HH + h;

    const int r0 = wi * 16 + lq;              // local row (and +8)
    const float ei0 = g_es[bh * NN + i0 + r0];
    const float ei1 = g_es[bh * NN + i0 + r0 + 8];
    const unsigned int* ap0 = g_adjp + ((size_t)b * NN + i0 + r0) * (NN / 32) + l3;
    const unsigned int* ap1 = ap0 + 8 * (NN / 32);

    const uint32_t wh_sb = smem_u32(wh_s);
    const uint32_t ed_sb = smem_u32(ed_s);
    const float4* whsrc0 = (const float4*)g_Wh + bh * NN * 8;
    const float4* edsrc0 = (const float4*)(g_ed + bh * NN);

    float acc[4][4] = {};
    float den0 = 0.f, den1 = 0.f;

    // stage half-tile ht into buffer bufi
#define STAGE(ht, bufi) do {                                                  \
        const uint32_t wdst = wh_sb + (bufi) * (HT * WSTRIDE * 4);            \
        const float4* wsrc = whsrc0 + (size_t)(ht) * HT * 8;                  \
        _Pragma("unroll")                                                     \
        for (int l = 0; l < 4; l++) {                                         \
            const int idx = t + l * 128;                                      \
            const int jj = idx >> 3, d4 = idx & 7;                            \
            cp16(wdst + jj * (WSTRIDE * 4) + d4 * 16, wsrc + jj * 8 + d4);    \
        }                                                                     \
        if (t < 16) cp16(ed_sb + (bufi) * (HT * 4) + t * 16,                  \
                         edsrc0 + (size_t)(ht) * (HT / 4) + t);               \
    } while (0)

    STAGE(0, 0);
    CP_COMMIT();
    unsigned int w0c = ap0[0], w1c = ap1[0];
    unsigned int w0n = 0, w1n = 0;

    for (int g = 0; g < 16; g++) {
        // ---- phase A: compute buf0 (rows 128g .. 128g+63), stage buf1 ----
        if (g) __syncthreads();               // done computing buf1 (prev phase B)
        STAGE(2 * g + 1, 1);
        CP_COMMIT();
        if (g + 1 < 16) { w0n = ap0[(g + 1) * 4]; w1n = ap1[(g + 1) * 4]; }
        CP_WAIT(1);
        __syncthreads();
        COMPUTE_HALF(0, (const uint32_t*)wh_s[0], ed_s[0], w0c, w1c);

        // ---- phase B: compute buf1 (rows 128g+64 ..), stage buf0 ----
        __syncthreads();                      // done computing buf0
        if (g + 1 < 16) {
            STAGE(2 * g + 2, 0);
            CP_COMMIT();
            CP_WAIT(1);
        } else {
            CP_WAIT(0);
        }
        __syncthreads();
        COMPUTE_HALF(8, (const uint32_t*)wh_s[1], ed_s[1], w0c, w1c);
        w0c = w0n; w1c = w1n;
    }

    den0 += __shfl_xor_sync(0xffffffffu, den0, 1);
    den0 += __shfl_xor_sync(0xffffffffu, den0, 2);
    den1 += __shfl_xor_sync(0xffffffffu, den1, 1);
    den1 += __shfl_xor_sync(0xffffffffu, den1, 2);
    const float rd0 = 1.f / den0;
    const float rd1 = 1.f / den1;

    // output cols: acc[nt][c01] -> d = 8*l3 + nt (c even), 8*l3+4+nt (c odd)
    float* orow0 = out + ((size_t)b * NN + i0 + r0) * (HH * DD) + h * DD + 8 * l3;
    float* orow1 = orow0 + 8 * (HH * DD);
    float4 v;
    v.x = acc[0][0] * rd0; v.y = acc[1][0] * rd0; v.z = acc[2][0] * rd0; v.w = acc[3][0] * rd0;
    *(float4*)orow0 = v;
    v.x = acc[0][1] * rd0; v.y = acc[1][1] * rd0; v.z = acc[2][1] * rd0; v.w = acc[3][1] * rd0;
    *(float4*)(orow0 + 4) = v;
    v.x = acc[0][2] * rd1; v.y = acc[1][2] * rd1; v.z = acc[2][2] * rd1; v.w = acc[3][2] * rd1;
    *(float4*)orow1 = v;
    v.x = acc[0][3] * rd1; v.y = acc[1][3] * rd1; v.z = acc[2][3] * rd1; v.w = acc[3][3] * rd1;
    *(float4*)(orow1 + 4) = v;
}

extern "C" void kernel_launch(void* const* d_in, const int* in_sizes, int n_in,
                              void* d_out, int out_size) {
    const float* x   = (const float*)d_in[0];
    const int*   adj = (const int*)d_in[1];
    const float* W   = (const float*)d_in[2];
    const float* a   = (const float*)d_in[3];
    float* out = (float*)d_out;

    cudaFuncSetAttribute(k1_proj, cudaFuncAttributeMaxDynamicSharedMemorySize, 98304);

    k0_pack<<<1024, 256>>>(adj);
    k1_proj<<<dim3(128, 8), 256, 98304>>>(x, W, a);
    k2_attn<<<dim3(32, HH, BB), 128>>>(out);
}

// round 13
// speedup vs baseline: 5.6992x; 1.0289x over previous
#include <cuda_runtime.h>
#include <cstdint>

#define BB 4
#define NN 2048
#define INF 256
#define HH 8
#define DD 32
#define LOG2E 1.44269504f
#define HT 64                 // half-tile rows
#define WSTRIDE 40            // padded row stride (words): conflict-free LDS.128
#define FONE 0x3f800000u      // 1.0f bits (exact in tf32)

// scratch (allocation-free rule: __device__ globals)
__device__ float g_Wh[BB*HH*NN*DD];            // [b][h][n][d]
__device__ float g_es[BB*HH*NN];               // e_i * log2e
__device__ float g_edp[BB*HH*NN*2];            // (2^ej, 2^(0.2 ej)) pairs, grouped layout
__device__ unsigned int g_adjp[BB*NN*(NN/32)]; // packed adj bits, interleaved layout

__device__ __forceinline__ float ex2(float x) {
    float r; asm("ex2.approx.ftz.f32 %0, %1;" : "=f"(r) : "f"(x)); return r;
}
__device__ __forceinline__ uint32_t smem_u32(const void* p) {
    uint32_t a;
    asm("{ .reg .u64 t; cvta.to.shared.u64 t, %1; cvt.u32.u64 %0, t; }" : "=r"(a) : "l"(p));
    return a;
}
__device__ __forceinline__ void cp16(uint32_t dst, const void* src) {
    asm volatile("cp.async.cg.shared.global [%0], [%1], 16;" :: "r"(dst), "l"(src));
}
#define CP_COMMIT() asm volatile("cp.async.commit_group;" ::: "memory")
#define CP_WAIT(n)  asm volatile("cp.async.wait_group %0;" :: "n"(n) : "memory")

__device__ __forceinline__ void mma8(float* c, uint32_t a0, uint32_t a1,
                                     uint32_t a2, uint32_t a3,
                                     uint32_t b0, uint32_t b1) {
    asm("mma.sync.aligned.m16n8k8.row.col.f32.tf32.tf32.f32 "
        "{%0,%1,%2,%3}, {%4,%5,%6,%7}, {%8,%9}, {%0,%1,%2,%3};"
        : "+f"(c[0]), "+f"(c[1]), "+f"(c[2]), "+f"(c[3])
        : "r"(a0), "r"(a1), "r"(a2), "r"(a3), "r"(b0), "r"(b1));
}

// ---------------------------------------------------------------------------
// Kernel 0: pack adj -> interleaved bitmask. MLP-8 batched loads.
// Per 128-j group g: word g*4 + (j&3), bit (j>>2)&31. One warp per row.
// ---------------------------------------------------------------------------
__global__ __launch_bounds__(256) void k0_pack(const int* __restrict__ adj) {
    const int lane = threadIdx.x & 31;
    const int row  = blockIdx.x * 8 + (threadIdx.x >> 5);   // 0..8191
    const int4* src = (const int4*)(adj + (size_t)row * NN) + lane;
    unsigned int* dst = g_adjp + (size_t)row * (NN / 32);
#pragma unroll
    for (int g = 0; g < 16; g += 8) {
        int4 v[8];
#pragma unroll
        for (int q = 0; q < 8; q++) v[q] = src[(g + q) * 32];
#pragma unroll
        for (int q = 0; q < 8; q++) {
            const unsigned int b0 = __ballot_sync(0xffffffffu, v[q].x != 0);
            const unsigned int b1 = __ballot_sync(0xffffffffu, v[q].y != 0);
            const unsigned int b2 = __ballot_sync(0xffffffffu, v[q].z != 0);
            const unsigned int b3 = __ballot_sync(0xffffffffu, v[q].w != 0);
            if (lane == 0) *(uint4*)(dst + (g + q) * 4) = make_uint4(b0, b1, b2, b3);
        }
    }
}

// ---------------------------------------------------------------------------
// Kernel 1: Wh = x @ W, e = Wh·a. es stored *log2e; ed stored as factored
// pairs (2^ej, 2^(0.2 ej)) in the grouped layout:
//   group g=n>>7, c=(n>>3)&15, pos=(n&3)*2+((n>>2)&1), idx=g*256+c*16+pos*2.
// ---------------------------------------------------------------------------
__global__ __launch_bounds__(256) void k1_proj(const float* __restrict__ x,
                                               const float* __restrict__ W,
                                               const float* __restrict__ a) {
    extern __shared__ float sm[];
    float* xs = sm;
    float* Ws = sm + 64 * INF;
    const int h  = blockIdx.y;
    const int b  = blockIdx.x >> 5;
    const int n0 = (blockIdx.x & 31) * 64;
    const int t  = threadIdx.x;

    const float4* xg = (const float4*)(x + ((size_t)b * NN + n0) * INF);
    float4* xs4 = (float4*)xs;
#pragma unroll
    for (int l = 0; l < 16; l++) xs4[t + l * 256] = xg[t + l * 256];
    const float4* wg = (const float4*)(W + (size_t)h * INF * DD);
    float4* ws4 = (float4*)Ws;
#pragma unroll
    for (int l = 0; l < 8; l++) ws4[t + l * 256] = wg[t + l * 256];
    __syncthreads();

    const int d = t & 31;
    const int g = t >> 5;
    float acc[8];
#pragma unroll
    for (int r = 0; r < 8; r++) acc[r] = 0.f;

    for (int kq = 0; kq < INF / 4; kq++) {
        const float w0 = Ws[(kq * 4 + 0) * DD + d];
        const float w1 = Ws[(kq * 4 + 1) * DD + d];
        const float w2 = Ws[(kq * 4 + 2) * DD + d];
        const float w3 = Ws[(kq * 4 + 3) * DD + d];
#pragma unroll
        for (int r = 0; r < 8; r++) {
            const float4 xv = *(const float4*)&xs[(g * 8 + r) * INF + kq * 4];
            acc[r] = fmaf(xv.x, w0, fmaf(xv.y, w1, fmaf(xv.z, w2, fmaf(xv.w, w3, acc[r]))));
        }
    }

    const float asrc = a[h * 2 * DD + d];
    const float adst = a[h * 2 * DD + DD + d];
#pragma unroll
    for (int r = 0; r < 8; r++) {
        const int n = n0 + g * 8 + r;
        g_Wh[(((size_t)b * HH + h) * NN + n) * DD + d] = acc[r];
        float es = acc[r] * asrc;
        float ed = acc[r] * adst;
#pragma unroll
        for (int off = 16; off; off >>= 1) {
            es += __shfl_xor_sync(0xffffffffu, es, off);
            ed += __shfl_xor_sync(0xffffffffu, ed, off);
        }
        if (d == 0) {
            g_es[((size_t)b * HH + h) * NN + n] = es * LOG2E;
            const float ejl = ed * LOG2E;
            const int idx = (n >> 7) * 256 + (((n >> 3) & 15) * 16)
                          + ((n & 3) * 2 + ((n >> 2) & 1)) * 2;
            float* ep = g_edp + ((size_t)b * HH + h) * (NN * 2) + idx;
            ep[0] = ex2(ejl);
            ep[1] = ex2(0.2f * ejl);
        }
    }
}

// ---------------------------------------------------------------------------
// Kernel 2: PV via mma.sync tf32 m16n8k8, MUFU-free inner loop:
//   p = mask ? max(Ei+ * Ej+, Ei- * Ej-) : 0     (exact leaky-softmax factoring)
// Denominator = 5th MMA vs B=1 (identical tf32 truncation as numerator).
// Half-tile (64j) double-buffered cp.async. 22KB smem.
// ---------------------------------------------------------------------------
#define COMPUTE_HALF(CB, whp, edp, w0, w1)                                    \
    _Pragma("unroll")                                                         \
    for (int c = 0; c < 8; c++) {                                             \
        const float4 e = *(const float4*)&(edp)[c * 16 + l3 * 4];             \
        const float t00 = eip0 * e.x, u00 = eim0 * e.y;                       \
        const float t01 = eip0 * e.z, u01 = eim0 * e.w;                       \
        const float t10 = eip1 * e.x, u10 = eim1 * e.y;                       \
        const float t11 = eip1 * e.z, u11 = eim1 * e.w;                       \
        const float p00 = ((w0) & (1u << (2 * ((CB) + c)))) ? fmaxf(t00, u00) : 0.f; \
        const float p01 = ((w0) & (2u << (2 * ((CB) + c)))) ? fmaxf(t01, u01) : 0.f; \
        const float p10 = ((w1) & (1u << (2 * ((CB) + c)))) ? fmaxf(t10, u10) : 0.f; \
        const float p11 = ((w1) & (2u << (2 * ((CB) + c)))) ? fmaxf(t11, u11) : 0.f; \
        const uint32_t a0 = __float_as_uint(p00);                             \
        const uint32_t a2 = __float_as_uint(p01);                             \
        const uint32_t a1 = __float_as_uint(p10);                             \
        const uint32_t a3 = __float_as_uint(p11);                             \
        const uint32_t* wp = (whp) + (c * 8 + l3) * WSTRIDE + lq * 4;         \
        const uint4 B0 = *(const uint4*)wp;                                   \
        const uint4 B1 = *(const uint4*)(wp + 4 * WSTRIDE);                   \
        mma8(acc[0], a0, a1, a2, a3, B0.x, B1.x);                             \
        mma8(acc[1], a0, a1, a2, a3, B0.y, B1.y);                             \
        mma8(acc[2], a0, a1, a2, a3, B0.z, B1.z);                             \
        mma8(acc[3], a0, a1, a2, a3, B0.w, B1.w);                             \
        mma8(accd,   a0, a1, a2, a3, FONE, FONE);                             \
    }

__global__ __launch_bounds__(128, 7) void k2_attn(float* __restrict__ out) {
    __shared__ float wh_s[2][HT * WSTRIDE];   // raw fp32 Wh half-tiles, 2 x 10KB
    __shared__ float ed_s[2][HT * 2];         // (Ej+, Ej-) pair halves

    const int t    = threadIdx.x;
    const int lane = t & 31;
    const int wi   = t >> 5;                  // 0..3
    const int l3   = lane & 3;
    const int lq   = lane >> 2;
    const int h  = blockIdx.y;
    const int b  = blockIdx.z;
    const int i0 = blockIdx.x * 64;
    const size_t bh = (size_t)b * HH + h;

    const int r0 = wi * 16 + lq;              // local row (and +8)
    const float ei0 = g_es[bh * NN + i0 + r0];
    const float ei1 = g_es[bh * NN + i0 + r0 + 8];
    const float eip0 = ex2(ei0), eim0 = ex2(0.2f * ei0);
    const float eip1 = ex2(ei1), eim1 = ex2(0.2f * ei1);
    const unsigned int* ap0 = g_adjp + ((size_t)b * NN + i0 + r0) * (NN / 32) + l3;
    const unsigned int* ap1 = ap0 + 8 * (NN / 32);

    const uint32_t wh_sb = smem_u32(wh_s);
    const uint32_t ed_sb = smem_u32(ed_s);
    const float4* whsrc0 = (const float4*)g_Wh + bh * NN * 8;
    const float4* edsrc0 = (const float4*)(g_edp + bh * (NN * 2));

    float acc[4][4] = {};
    float accd[4] = {};

    // stage half-tile ht into buffer bufi
#define STAGE(ht, bufi) do {                                                  \
        const uint32_t wdst = wh_sb + (bufi) * (HT * WSTRIDE * 4);            \
        const float4* wsrc = whsrc0 + (size_t)(ht) * HT * 8;                  \
        _Pragma("unroll")                                                     \
        for (int l = 0; l < 4; l++) {                                         \
            const int idx = t + l * 128;                                      \
            const int jj = idx >> 3, d4 = idx & 7;                            \
            cp16(wdst + jj * (WSTRIDE * 4) + d4 * 16, wsrc + jj * 8 + d4);    \
        }                                                                     \
        if (t < 32) cp16(ed_sb + (bufi) * (HT * 8) + t * 16,                  \
                         edsrc0 + (size_t)(ht) * (HT / 2) + t);               \
    } while (0)

    STAGE(0, 0);
    CP_COMMIT();
    unsigned int w0c = ap0[0], w1c = ap1[0];
    unsigned int w0n = 0, w1n = 0;

    for (int g = 0; g < 16; g++) {
        // ---- phase A: compute buf0, stage buf1 ----
        if (g) __syncthreads();               // done computing buf1 (prev phase B)
        STAGE(2 * g + 1, 1);
        CP_COMMIT();
        if (g + 1 < 16) { w0n = ap0[(g + 1) * 4]; w1n = ap1[(g + 1) * 4]; }
        CP_WAIT(1);
        __syncthreads();
        COMPUTE_HALF(0, (const uint32_t*)wh_s[0], ed_s[0], w0c, w1c);

        // ---- phase B: compute buf1, stage buf0 ----
        __syncthreads();                      // done computing buf0
        if (g + 1 < 16) {
            STAGE(2 * g + 2, 0);
            CP_COMMIT();
            CP_WAIT(1);
        } else {
            CP_WAIT(0);
        }
        __syncthreads();
        COMPUTE_HALF(8, (const uint32_t*)wh_s[1], ed_s[1], w0c, w1c);
        w0c = w0n; w1c = w1n;
    }

    // row sums came from the ones-MMA: accd[0] = den(r0), accd[2] = den(r0+8)
    const float rd0 = 1.f / accd[0];
    const float rd1 = 1.f / accd[2];

    // output cols: acc[nt][c01] -> d = 8*l3 + nt (c even), 8*l3+4+nt (c odd)
    float* orow0 = out + ((size_t)b * NN + i0 + r0) * (HH * DD) + h * DD + 8 * l3;
    float* orow1 = orow0 + 8 * (HH * DD);
    float4 v;
    v.x = acc[0][0] * rd0; v.y = acc[1][0] * rd0; v.z = acc[2][0] * rd0; v.w = acc[3][0] * rd0;
    *(float4*)orow0 = v;
    v.x = acc[0][1] * rd0; v.y = acc[1][1] * rd0; v.z = acc[2][1] * rd0; v.w = acc[3][1] * rd0;
    *(float4*)(orow0 + 4) = v;
    v.x = acc[0][2] * rd1; v.y = acc[1][2] * rd1; v.z = acc[2][2] * rd1; v.w = acc[3][2] * rd1;
    *(float4*)orow1 = v;
    v.x = acc[0][3] * rd1; v.y = acc[1][3] * rd1; v.z = acc[2][3] * rd1; v.w = acc[3][3] * rd1;
    *(float4*)(orow1 + 4) = v;
}

extern "C" void kernel_launch(void* const* d_in, const int* in_sizes, int n_in,
                              void* d_out, int out_size) {
    const float* x   = (const float*)d_in[0];
    const int*   adj = (const int*)d_in[1];
    const float* W   = (const float*)d_in[2];
    const float* a   = (const float*)d_in[3];
    float* out = (float*)d_out;

    cudaFuncSetAttribute(k1_proj, cudaFuncAttributeMaxDynamicSharedMemorySize, 98304);

    k0_pack<<<1024, 256>>>(adj);
    k1_proj<<<dim3(128, 8), 256, 98304>>>(x, W, a);
    k2_attn<<<dim3(32, HH, BB), 128>>>(out);
}

// round 15
// speedup vs baseline: 7.1161x; 1.2486x over previous
#include <cuda_runtime.h>
#include <cstdint>

#define BB 4
#define NN 2048
#define INF 256
#define HH 8
#define DD 32
#define LOG2E 1.44269504f
#define BSTRIDE 40            // wh pair-row stride (words), conflict-free LDS.128
#define HONE 0x3C003C00u      // (1.0h, 1.0h)

// scratch (allocation-free rule: __device__ globals)
__device__ uint32_t g_Whh[BB*HH*(NN/2)*DD];    // f16x2 (Wh[n][d], Wh[n+1][d])
__device__ float g_es[BB*HH*NN];               // e_i * log2e
__device__ float g_edp[BB*HH*NN*2];            // (2^ejL, 2^(0.2 ejL)) per j, natural
__device__ unsigned int g_adjp[BB*NN*(NN/32)]; // packed adj bits, interleaved layout

__device__ __forceinline__ float ex2(float x) {
    float r; asm("ex2.approx.ftz.f32 %0, %1;" : "=f"(r) : "f"(x)); return r;
}
__device__ __forceinline__ uint32_t packh2(float lo, float hi) {
    uint32_t r;  // PTX: cvt.f16x2 d, a, b -> a=upper, b=lower
    asm("cvt.rn.f16x2.f32 %0, %1, %2;" : "=r"(r) : "f"(hi), "f"(lo));
    return r;
}
__device__ __forceinline__ uint32_t smem_u32(const void* p) {
    uint32_t a;
    asm("{ .reg .u64 t; cvta.to.shared.u64 t, %1; cvt.u32.u64 %0, t; }" : "=r"(a) : "l"(p));
    return a;
}
__device__ __forceinline__ void cp16(uint32_t dst, const void* src) {
    asm volatile("cp.async.cg.shared.global [%0], [%1], 16;" :: "r"(dst), "l"(src));
}
#define CP_COMMIT() asm volatile("cp.async.commit_group;" ::: "memory")
#define CP_WAIT(n)  asm volatile("cp.async.wait_group %0;" :: "n"(n) : "memory")

__device__ __forceinline__ void mma16(float* c, uint32_t a0, uint32_t a1,
                                      uint32_t a2, uint32_t a3,
                                      uint32_t b0, uint32_t b1) {
    asm("mma.sync.aligned.m16n8k16.row.col.f32.f16.f16.f32 "
        "{%0,%1,%2,%3}, {%4,%5,%6,%7}, {%8,%9}, {%0,%1,%2,%3};"
        : "+f"(c[0]), "+f"(c[1]), "+f"(c[2]), "+f"(c[3])
        : "r"(a0), "r"(a1), "r"(a2), "r"(a3), "r"(b0), "r"(b1));
}

// ---------------------------------------------------------------------------
// Kernel 0: pack adj -> interleaved bitmask (per 128-group: word j&3, bit j>>2)
// ---------------------------------------------------------------------------
__global__ __launch_bounds__(256) void k0_pack(const int* __restrict__ adj) {
    const int lane = threadIdx.x & 31;
    const int row  = blockIdx.x * 8 + (threadIdx.x >> 5);   // 0..8191
    const int4* src = (const int4*)(adj + (size_t)row * NN) + lane;
    unsigned int* dst = g_adjp + (size_t)row * (NN / 32);
#pragma unroll
    for (int g = 0; g < 16; g += 8) {
        int4 v[8];
#pragma unroll
        for (int q = 0; q < 8; q++) v[q] = src[(g + q) * 32];
#pragma unroll
        for (int q = 0; q < 8; q++) {
            const unsigned int b0 = __ballot_sync(0xffffffffu, v[q].x != 0);
            const unsigned int b1 = __ballot_sync(0xffffffffu, v[q].y != 0);
            const unsigned int b2 = __ballot_sync(0xffffffffu, v[q].z != 0);
            const unsigned int b3 = __ballot_sync(0xffffffffu, v[q].w != 0);
            if (lane == 0) *(uint4*)(dst + (g + q) * 4) = make_uint4(b0, b1, b2, b3);
        }
    }
}

// ---------------------------------------------------------------------------
// Kernel 1: Wh = x @ W (stored as fp16 row-pairs), e = Wh·a; es *= log2e;
// ed stored as factored pairs (2^ejL, 2^(0.2 ejL)) at natural index n*2.
// ---------------------------------------------------------------------------
__global__ __launch_bounds__(256) void k1_proj(const float* __restrict__ x,
                                               const float* __restrict__ W,
                                               const float* __restrict__ a) {
    extern __shared__ float sm[];
    float* xs = sm;
    float* Ws = sm + 64 * INF;
    const int h  = blockIdx.y;
    const int b  = blockIdx.x >> 5;
    const int n0 = (blockIdx.x & 31) * 64;
    const int t  = threadIdx.x;
    const size_t bh = (size_t)b * HH + h;

    const float4* xg = (const float4*)(x + ((size_t)b * NN + n0) * INF);
    float4* xs4 = (float4*)xs;
#pragma unroll
    for (int l = 0; l < 16; l++) xs4[t + l * 256] = xg[t + l * 256];
    const float4* wg = (const float4*)(W + (size_t)h * INF * DD);
    float4* ws4 = (float4*)Ws;
#pragma unroll
    for (int l = 0; l < 8; l++) ws4[t + l * 256] = wg[t + l * 256];
    __syncthreads();

    const int d = t & 31;
    const int g = t >> 5;
    float acc[8];
#pragma unroll
    for (int r = 0; r < 8; r++) acc[r] = 0.f;

    for (int kq = 0; kq < INF / 4; kq++) {
        const float w0 = Ws[(kq * 4 + 0) * DD + d];
        const float w1 = Ws[(kq * 4 + 1) * DD + d];
        const float w2 = Ws[(kq * 4 + 2) * DD + d];
        const float w3 = Ws[(kq * 4 + 3) * DD + d];
#pragma unroll
        for (int r = 0; r < 8; r++) {
            const float4 xv = *(const float4*)&xs[(g * 8 + r) * INF + kq * 4];
            acc[r] = fmaf(xv.x, w0, fmaf(xv.y, w1, fmaf(xv.z, w2, fmaf(xv.w, w3, acc[r]))));
        }
    }

    // fp16 pair-packed Wh: word [(bh*NN+n)/2][d] = (Wh[n], Wh[n+1])
#pragma unroll
    for (int r = 0; r < 8; r += 2) {
        const int n = n0 + g * 8 + r;
        g_Whh[((bh * NN + n) >> 1) * DD + d] = packh2(acc[r], acc[r + 1]);
    }

    const float asrc = a[h * 2 * DD + d];
    const float adst = a[h * 2 * DD + DD + d];
#pragma unroll
    for (int r = 0; r < 8; r++) {
        const int n = n0 + g * 8 + r;
        float es = acc[r] * asrc;
        float ed = acc[r] * adst;
#pragma unroll
        for (int off = 16; off; off >>= 1) {
            es += __shfl_xor_sync(0xffffffffu, es, off);
            ed += __shfl_xor_sync(0xffffffffu, ed, off);
        }
        if (d == 0) {
            g_es[bh * NN + n] = es * LOG2E;
            const float ejl = ed * LOG2E;
            float2 p;
            p.x = ex2(ejl);
            p.y = ex2(0.2f * ejl);
            *(float2*)(g_edp + bh * (NN * 2) + n * 2) = p;
        }
    }
}

// ---------------------------------------------------------------------------
// Kernel 2: PV via mma.sync fp16 m16n8k16 — half the MMA dispatches of tf32 k8.
//   p = mask ? max(Eip*Ejp, Eim*Ejm) : 0, globally scaled 2^-6 (cancels).
// Denominator = 5th MMA vs B=1. Half-tile (64j) double-buffered cp.async.
// ---------------------------------------------------------------------------
#define COMPUTE_HALF(CB, whp, edp)                                            \
    _Pragma("unroll")                                                         \
    for (int c = 0; c < 4; c++) {                                             \
        const int cc = (CB) + c;                                              \
        const float4 e1 = *(const float4*)&(edp)[c * 32 + l3 * 4];            \
        const float4 e2 = *(const float4*)&(edp)[c * 32 + 16 + l3 * 4];       \
        float p00 = fmaxf(eip0 * e1.x, eim0 * e1.y);                          \
        float p01 = fmaxf(eip0 * e1.z, eim0 * e1.w);                          \
        float p10 = fmaxf(eip1 * e1.x, eim1 * e1.y);                          \
        float p11 = fmaxf(eip1 * e1.z, eim1 * e1.w);                          \
        float p02 = fmaxf(eip0 * e2.x, eim0 * e2.y);                          \
        float p03 = fmaxf(eip0 * e2.z, eim0 * e2.w);                          \
        float p12 = fmaxf(eip1 * e2.x, eim1 * e2.y);                          \
        float p13 = fmaxf(eip1 * e2.z, eim1 * e2.w);                          \
        p00 = (qx0 & (1u << (4 * cc))) ? p00 : 0.f;                           \
        p01 = (qy0 & (1u << (4 * cc))) ? p01 : 0.f;                           \
        p02 = (qx0 & (4u << (4 * cc))) ? p02 : 0.f;                           \
        p03 = (qy0 & (4u << (4 * cc))) ? p03 : 0.f;                           \
        p10 = (qx1 & (1u << (4 * cc))) ? p10 : 0.f;                           \
        p11 = (qy1 & (1u << (4 * cc))) ? p11 : 0.f;                           \
        p12 = (qx1 & (4u << (4 * cc))) ? p12 : 0.f;                           \
        p13 = (qy1 & (4u << (4 * cc))) ? p13 : 0.f;                           \
        const uint32_t a0 = packh2(p00, p01);                                 \
        const uint32_t a1 = packh2(p10, p11);                                 \
        const uint32_t a2 = packh2(p02, p03);                                 \
        const uint32_t a3 = packh2(p12, p13);                                 \
        const uint32_t* wp = (whp) + (c * 8 + l3) * BSTRIDE + lq * 4;         \
        const uint4 B0 = *(const uint4*)wp;                                   \
        const uint4 B1 = *(const uint4*)(wp + 4 * BSTRIDE);                   \
        mma16(acc[0], a0, a1, a2, a3, B0.x, B1.x);                            \
        mma16(acc[1], a0, a1, a2, a3, B0.y, B1.y);                            \
        mma16(acc[2], a0, a1, a2, a3, B0.z, B1.z);                            \
        mma16(acc[3], a0, a1, a2, a3, B0.w, B1.w);                            \
        mma16(accd,   a0, a1, a2, a3, HONE, HONE);                            \
    }

__global__ __launch_bounds__(128) void k2_attn(float* __restrict__ out) {
    __shared__ uint32_t wh_s[2][32 * BSTRIDE];  // f16x2 pair-rows, 2 x 5KB
    __shared__ float    ed_s[2][128];           // (Ejp,Ejm) per j, 2 x 512B

    const int t    = threadIdx.x;
    const int lane = t & 31;
    const int wi   = t >> 5;                  // 0..3
    const int l3   = lane & 3;
    const int lq   = lane >> 2;
    const int dlt  = l3 >> 1;
    const int h  = blockIdx.y;
    const int b  = blockIdx.z;
    const int i0 = blockIdx.x * 64;
    const size_t bh = (size_t)b * HH + h;

    const int r0 = wi * 16 + lq;              // local row (and +8)
    const float esL0 = g_es[bh * NN + i0 + r0];
    const float esL1 = g_es[bh * NN + i0 + r0 + 8];
    const float eip0 = ex2(esL0 - 6.f), eim0 = ex2(0.2f * esL0 - 6.f);
    const float eip1 = ex2(esL1 - 6.f), eim1 = ex2(0.2f * esL1 - 6.f);

    // per-group mask pair: words g*4 + 2*(l3&1), pre-shifted by l3>>1
    const uint2* mp0 = (const uint2*)(g_adjp + ((size_t)b * NN + i0 + r0) * 64 + 2 * (l3 & 1));
    const uint2* mp1 = (const uint2*)((const unsigned int*)mp0 + 8 * 64);

    const uint32_t wh_sb = smem_u32(wh_s);
    const uint32_t ed_sb = smem_u32(ed_s);
    const uint4* whsrc = (const uint4*)(g_Whh + bh * (NN / 2) * DD);
    const uint4* edsrc = (const uint4*)(g_edp + bh * (NN * 2));

    float acc[4][4] = {};
    float accd[4] = {};

    // stage half-tile ht (64 j) into buffer bufi
#define STAGE(ht, bufi) do {                                                  \
        const uint32_t wdst = wh_sb + (bufi) * (32 * BSTRIDE * 4);            \
        const uint4* wsrc = whsrc + (size_t)(ht) * 256;                       \
        _Pragma("unroll")                                                     \
        for (int l = 0; l < 2; l++) {                                         \
            const int idx = t + l * 128;                                      \
            const int jp = idx >> 3, d4 = idx & 7;                            \
            cp16(wdst + jp * (BSTRIDE * 4) + d4 * 16, wsrc + idx);            \
        }                                                                     \
        if (t < 32) cp16(ed_sb + (bufi) * 512 + t * 16,                       \
                         edsrc + (size_t)(ht) * 32 + t);                      \
    } while (0)

    STAGE(0, 0);
    CP_COMMIT();
    uint2 q0 = mp0[0], q1 = mp1[0];
    uint32_t qx0 = q0.x >> dlt, qy0 = q0.y >> dlt;
    uint32_t qx1 = q1.x >> dlt, qy1 = q1.y >> dlt;
    uint2 q0n = make_uint2(0, 0), q1n = make_uint2(0, 0);

    for (int g = 0; g < 16; g++) {
        // ---- phase A: compute buf0 (j = 128g..+63), stage buf1 ----
        if (g) __syncthreads();               // done computing buf1 (prev phase B)
        STAGE(2 * g + 1, 1);
        CP_COMMIT();
        if (g + 1 < 16) { q0n = mp0[(g + 1) * 2]; q1n = mp1[(g + 1) * 2]; }
        CP_WAIT(1);
        __syncthreads();
        COMPUTE_HALF(0, (const uint32_t*)wh_s[0], ed_s[0]);

        // ---- phase B: compute buf1 (j = 128g+64..), stage buf0 ----
        __syncthreads();                      // done computing buf0
        if (g + 1 < 16) {
            STAGE(2 * g + 2, 0);
            CP_COMMIT();
            CP_WAIT(1);
        } else {
            CP_WAIT(0);
        }
        __syncthreads();
        COMPUTE_HALF(4, (const uint32_t*)wh_s[1], ed_s[1]);
        qx0 = q0n.x >> dlt; qy0 = q0n.y >> dlt;
        qx1 = q1n.x >> dlt; qy1 = q1n.y >> dlt;
    }

    // denominators from the ones-MMA: accd[0]=den(r0), accd[2]=den(r0+8)
    const float rd0 = 1.f / accd[0];
    const float rd1 = 1.f / accd[2];

    // output: acc[nt][c01] -> d = 8*l3 + nt (c even), 8*l3+4+nt (c odd)
    float* orow0 = out + ((size_t)b * NN + i0 + r0) * (HH * DD) + h * DD + 8 * l3;
    float* orow1 = orow0 + 8 * (HH * DD);
    float4 v;
    v.x = acc[0][0] * rd0; v.y = acc[1][0] * rd0; v.z = acc[2][0] * rd0; v.w = acc[3][0] * rd0;
    *(float4*)orow0 = v;
    v.x = acc[0][1] * rd0; v.y = acc[1][1] * rd0; v.z = acc[2][1] * rd0; v.w = acc[3][1] * rd0;
    *(float4*)(orow0 + 4) = v;
    v.x = acc[0][2] * rd1; v.y = acc[1][2] * rd1; v.z = acc[2][2] * rd1; v.w = acc[3][2] * rd1;
    *(float4*)orow1 = v;
    v.x = acc[0][3] * rd1; v.y = acc[1][3] * rd1; v.z = acc[2][3] * rd1; v.w = acc[3][3] * rd1;
    *(float4*)(orow1 + 4) = v;
}

extern "C" void kernel_launch(void* const* d_in, const int* in_sizes, int n_in,
                              void* d_out, int out_size) {
    const float* x   = (const float*)d_in[0];
    const int*   adj = (const int*)d_in[1];
    const float* W   = (const float*)d_in[2];
    const float* a   = (const float*)d_in[3];
    float* out = (float*)d_out;

    cudaFuncSetAttribute(k1_proj, cudaFuncAttributeMaxDynamicSharedMemorySize, 98304);

    k0_pack<<<1024, 256>>>(adj);
    k1_proj<<<dim3(128, 8), 256, 98304>>>(x, W, a);
    k2_attn<<<dim3(32, HH, BB), 128>>>(out);
}